// round 11
// baseline (speedup 1.0000x reference)
#include <cuda_runtime.h>
#include <math.h>
#include <stdint.h>

// Problem constants
#define B   4
#define CIN 256
#define C   128
#define HW  64
#define N   4096          // HW*HW
#define CQK 16
#define ESPLIT 16         // CAM energy split-k slices

// ---------------- scratch (device globals; no allocation) ----------------
__device__ float g_y[B * C * N];        // conv out, then feat (in-place) : 8 MB
__device__ float g_scale[C];
__device__ float g_shift[C];
__device__ float g_bnp0[512];
__device__ float g_bnp1[512];
__device__ uint32_t g_q[B * CQK * N];   // tf32 bits
__device__ uint32_t g_k[B * CQK * N];   // tf32 bits
__device__ uint32_t g_v[B * C * N];     // tf32 bits : 8 MB
__device__ float g_e[B * C * C];        // CAM attn
__device__ float g_ep[ESPLIT * B * C * C];  // CAM energy partials : 4 MB
__device__ uint32_t g_w2hi[9 * 128 * 256];  // conv weights, tf32 hi, [off][co][ci]
__device__ uint32_t g_w2lo[9 * 128 * 256];  // tf32 residual

// ================= base-ISA tensor helpers (NO tcgen05 — plain sm_103) ======
__device__ __forceinline__ uint32_t f32_tf32(float f) {
    uint32_t r;
    asm("cvt.rna.tf32.f32 %0, %1;" : "=r"(r) : "f"(f));
    return r;
}
__device__ __forceinline__ float tanh_ap(float x) {
    float y;
    asm("tanh.approx.f32 %0, %1;" : "=f"(y) : "f"(x));
    return y;
}
// D += A(16x8 tf32) * B(8x8 tf32), fp32 accum
__device__ __forceinline__ void mma_tf32(float* d, const uint32_t* a, uint32_t b0, uint32_t b1) {
    asm volatile(
        "mma.sync.aligned.m16n8k8.row.col.f32.tf32.tf32.f32 "
        "{%0,%1,%2,%3}, {%4,%5,%6,%7}, {%8,%9}, {%0,%1,%2,%3};"
        : "+f"(d[0]), "+f"(d[1]), "+f"(d[2]), "+f"(d[3])
        : "r"(a[0]), "r"(a[1]), "r"(a[2]), "r"(a[3]), "r"(b0), "r"(b1));
}
// ldmatrix x4 (b16 view; loads 4 8x4-b32 matrices)
__device__ __forceinline__ void ldsm4(uint32_t* r, uint32_t saddr) {
    asm volatile("ldmatrix.sync.aligned.m8n8.x4.shared.b16 {%0,%1,%2,%3}, [%4];"
                 : "=r"(r[0]), "=r"(r[1]), "=r"(r[2]), "=r"(r[3]) : "r"(saddr));
}
__device__ __forceinline__ void cp16(uint32_t saddr, const void* g) {
    asm volatile("cp.async.cg.shared.global [%0], [%1], 16;" :: "r"(saddr), "l"(g));
}
__device__ __forceinline__ void cp_commit() {
    asm volatile("cp.async.commit_group;" ::: "memory");
}
template <int NN> __device__ __forceinline__ void cp_wait() {
    asm volatile("cp.async.wait_group %0;" :: "n"(NN) : "memory");
}

// ---------------- K0: weight prep: w -> tf32 hi/lo, [off][co][ci] ------------
__global__ void wprep_kernel(const float* __restrict__ w) {
    int i = blockIdx.x * 256 + threadIdx.x;
    if (i >= 9 * 128 * 256) return;
    int off = i >> 15;
    int rem = i & 32767;
    int co = rem >> 8, ci = rem & 255;
    float v = w[(co * 256 + ci) * 9 + off];
    uint32_t hi = f32_tf32(v);
    g_w2hi[i] = hi;
    g_w2lo[i] = f32_tf32(v - __uint_as_float(hi));
}

// ---------------- K1: 3x3 conv via mma.sync tf32 (3xTF32 split) --------------
// 88 KB smem -> 2 CTAs/SM -> single wave for grid 256.
#define XS_HI 0
#define XS_LO 6400
#define WS_HI 12800
#define WS_LO 17408
#define CONV_SMEM_WORDS 22016

__global__ __launch_bounds__(256)
void conv_tc_kernel(const float* __restrict__ x) {
    extern __shared__ uint32_t cs[];
    const int y = blockIdx.x, b = blockIdx.y;
    const int t = threadIdx.x;
    const int w = t >> 5, lane = t & 31;
    const int lq = lane >> 2, lr = lane & 3;
    const int cw = (w >> 1) * 32;
    const int pw = (w & 1) * 32;

    float acc[2][4][4];
#pragma unroll
    for (int ct = 0; ct < 2; ct++)
#pragma unroll
        for (int nt = 0; nt < 4; nt++)
#pragma unroll
            for (int i = 0; i < 4; i++) acc[ct][nt][i] = 0.f;

    for (int ci0 = 0; ci0 < CIN; ci0 += 32) {
        __syncthreads();
        for (int i = t; i < 32 * 198; i += 256) {
            int ci = i / 198, rem = i % 198;
            int yy = rem / 66, xx = rem % 66;
            int gy = y + yy - 1, gx = xx - 1;
            float v = 0.f;
            if (gy >= 0 && gy < HW && gx >= 0 && gx < HW)
                v = x[(((b * CIN + ci0 + ci) << 6) + gy) * 64 + gx];
            uint32_t hi = f32_tf32(v);
            int a = ci * 200 + yy * 66 + xx;
            cs[XS_HI + a] = hi;
            cs[XS_LO + a] = f32_tf32(v - __uint_as_float(hi));
        }

#pragma unroll 1
        for (int off = 0; off < 9; off++) {
            __syncthreads();
            {
                int base = (off << 15) + ci0;
#pragma unroll
                for (int p = 0; p < 16; p++) {
                    int i = t + p * 256;
                    int co = i >> 5, ci = i & 31;
                    int src = base + (co << 8) + ci;
                    cs[WS_HI + co * 36 + ci] = g_w2hi[src];
                    cs[WS_LO + co * 36 + ci] = g_w2lo[src];
                }
            }
            __syncthreads();
            const int ky = off / 3, kx = off % 3;
            const int xbase = ky * 66 + kx + pw;

#pragma unroll
            for (int ks = 0; ks < 4; ks++) {
                int k = ks * 8;
                uint32_t ahi[2][4], alo[2][4];
#pragma unroll
                for (int ct = 0; ct < 2; ct++) {
                    int r = (cw + ct * 16 + lq) * 36 + k + lr;
                    ahi[ct][0] = cs[WS_HI + r];
                    ahi[ct][1] = cs[WS_HI + r + 8 * 36];
                    ahi[ct][2] = cs[WS_HI + r + 4];
                    ahi[ct][3] = cs[WS_HI + r + 8 * 36 + 4];
                    alo[ct][0] = cs[WS_LO + r];
                    alo[ct][1] = cs[WS_LO + r + 8 * 36];
                    alo[ct][2] = cs[WS_LO + r + 4];
                    alo[ct][3] = cs[WS_LO + r + 8 * 36 + 4];
                }
#pragma unroll
                for (int nt = 0; nt < 4; nt++) {
                    int a0 = (k + lr) * 200 + xbase + nt * 8 + lq;
                    int a1 = a0 + 4 * 200;
                    uint32_t bh0 = cs[XS_HI + a0], bh1 = cs[XS_HI + a1];
                    uint32_t bl0 = cs[XS_LO + a0], bl1 = cs[XS_LO + a1];
#pragma unroll
                    for (int ct = 0; ct < 2; ct++) {
                        mma_tf32(acc[ct][nt], ahi[ct], bh0, bh1);
                        mma_tf32(acc[ct][nt], ahi[ct], bl0, bl1);
                        mma_tf32(acc[ct][nt], alo[ct], bh0, bh1);
                    }
                }
            }
        }
    }

#pragma unroll
    for (int ct = 0; ct < 2; ct++) {
#pragma unroll
        for (int rr = 0; rr < 2; rr++) {
            int co = cw + ct * 16 + lq + rr * 8;
            float* row = &g_y[((b * C + co) << 12) + (y << 6) + pw];
#pragma unroll
            for (int nt = 0; nt < 4; nt++) {
                int m = nt * 8 + lr * 2;
                float2 vv;
                vv.x = acc[ct][nt][rr * 2];
                vv.y = acc[ct][nt][rr * 2 + 1];
                *(float2*)&row[m] = vv;
            }
        }
    }
}

// ---------------- K2a: per-(channel,batch) partial stats ----------------
__global__ void bnstats1_kernel() {
    const int blk = blockIdx.x;            // 512 = c*4 + b
    const int c = blk >> 2, b = blk & 3;
    const int t = threadIdx.x;
    const float4* p = (const float4*)&g_y[(b * C + c) << 12];
    float s = 0.f, ss = 0.f;
#pragma unroll
    for (int i = 0; i < 4; i++) {
        float4 v = p[t + i * 256];
        s += v.x + v.y + v.z + v.w;
        ss += v.x * v.x + v.y * v.y + v.z * v.z + v.w * v.w;
    }
    __shared__ float r1[256], r2[256];
    r1[t] = s; r2[t] = ss;
    __syncthreads();
    for (int off = 128; off; off >>= 1) {
        if (t < off) { r1[t] += r1[t + off]; r2[t] += r2[t + off]; }
        __syncthreads();
    }
    if (t == 0) { g_bnp0[blk] = r1[0]; g_bnp1[blk] = r2[0]; }
}

// ---------------- K2b: finalize scale/shift ----------------
__global__ void bnstats2_kernel(const float* __restrict__ gamma, const float* __restrict__ beta) {
    const int c = threadIdx.x;             // 128
    float s = 0.f, ss = 0.f;
#pragma unroll
    for (int b = 0; b < 4; b++) { s += g_bnp0[c * 4 + b]; ss += g_bnp1[c * 4 + b]; }
    const float inv = 1.f / (float)(B * N);
    float mean = s * inv;
    float var  = ss * inv - mean * mean;
    float istd = rsqrtf(var + 1e-5f);
    float sc = gamma[c] * istd;
    g_scale[c] = sc;
    g_shift[c] = beta[c] - mean * sc;
}

// ---------------- K3: BN + ReLU, d_out = 3*feat ----------------
__global__ void bnrelu_kernel(float* __restrict__ out) {
    const int total = B * C * N;
    for (int i = blockIdx.x * 256 + threadIdx.x; i < total; i += 2048 * 256) {
        int c = (i >> 12) & (C - 1);
        float v = fmaxf(g_y[i] * g_scale[c] + g_shift[c], 0.f);
        g_y[i] = v;
        out[i] = 3.f * v;
    }
}

// ---------------- K4: qkv via mma.sync tf32 ----------------------------------
#define QK_WS 0                       // W tf32 [o][c] pitch 132 : 21120 words
#define QK_FS 21120                   // f tf32 [c][n] pitch 72  : 9216 words
#define QK_BIAS 30336                 // 160 floats
#define QK_WORDS 30496

__global__ __launch_bounds__(320)
void qkv_mma_kernel(const float* __restrict__ qw, const float* __restrict__ qb,
                    const float* __restrict__ kw, const float* __restrict__ kb,
                    const float* __restrict__ vw, const float* __restrict__ vb) {
    extern __shared__ uint32_t qs_[];
    const int b = blockIdx.y, n0 = blockIdx.x * 64;
    const int t = threadIdx.x;
    const int w = t >> 5, lane = t & 31;
    const int lq = lane >> 2, lr = lane & 3;

    for (int i = t; i < 160 * 128; i += 320) {
        int o = i >> 7, c = i & 127;
        float wv = (o < 16) ? qw[o * C + c]
                 : (o < 32) ? kw[(o - 16) * C + c]
                            : vw[(o - 32) * C + c];
        qs_[QK_WS + o * 132 + c] = f32_tf32(wv);
    }
    if (t < 160)
        ((float*)(qs_ + QK_BIAS))[t] = (t < 16) ? qb[t] : (t < 32 ? kb[t - 16] : vb[t - 32]);
    for (int i = t; i < 8192; i += 320) {
        int c = i >> 6, n = i & 63;
        qs_[QK_FS + c * 72 + n] = f32_tf32(g_y[((b * C + c) << 12) + n0 + n]);
    }
    __syncthreads();

    const int o0 = w * 16;
    float acc[8][4];
#pragma unroll
    for (int nt = 0; nt < 8; nt++)
#pragma unroll
        for (int i = 0; i < 4; i++) acc[nt][i] = 0.f;

#pragma unroll
    for (int ks = 0; ks < 16; ks++) {
        const int k = ks * 8;
        uint32_t a[4];
        {
            int r = (o0 + lq) * 132 + k + lr;
            a[0] = qs_[QK_WS + r];
            a[1] = qs_[QK_WS + r + 8 * 132];
            a[2] = qs_[QK_WS + r + 4];
            a[3] = qs_[QK_WS + r + 8 * 132 + 4];
        }
#pragma unroll
        for (int nt = 0; nt < 8; nt++) {
            uint32_t b0 = qs_[QK_FS + (k + lr) * 72 + nt * 8 + lq];
            uint32_t b1 = qs_[QK_FS + (k + lr + 4) * 72 + nt * 8 + lq];
            mma_tf32(acc[nt], a, b0, b1);
        }
    }

    const float* bias = (const float*)(qs_ + QK_BIAS);
#pragma unroll
    for (int rr = 0; rr < 2; rr++) {
        int o = o0 + lq + rr * 8;
        float bi = bias[o];
        uint32_t* dst = (o < 16) ? &g_q[((b * CQK + o) << 12) + n0]
                      : (o < 32) ? &g_k[((b * CQK + o - 16) << 12) + n0]
                                 : &g_v[((b * C + o - 32) << 12) + n0];
#pragma unroll
        for (int nt = 0; nt < 8; nt++) {
            int n = nt * 8 + lr * 2;
            uint2 u;
            u.x = f32_tf32(acc[nt][rr * 2] + bi);
            u.y = f32_tf32(acc[nt][rr * 2 + 1] + bi);
            *(uint2*)&dst[n] = u;
        }
    }
}

// ---------------- K5: CAM energy via mma.sync tf32, 3x split, split-k --------
// ldmatrix fragment loads (pitch 68 == 4 mod 32 -> conflict-free).
#define CE_FH 0
#define CE_FL 8704
#define CE_WORDS 17408

__global__ __launch_bounds__(256)
void cam_energy_mma_kernel() {
    extern __shared__ uint32_t es[];
    const int b = blockIdx.y, s = blockIdx.x;
    const int nbase = s * (N / ESPLIT);
    const int t = threadIdx.x;
    const int w = t >> 5, lane = t & 31;
    const int lq = lane >> 2, lr = lane & 3;
    const int cw = (w & 3) * 32, dw = (w >> 2) * 64;
    const uint32_t sbase = (uint32_t)__cvta_generic_to_shared(es);

    // ldmatrix lane-address components
    const int aRow = lane & 15;                 // A: row within 16
    const int aCol = (lane >> 4) << 2;          // A: col sel 0/4
    const int bRow = ((lane >> 4) << 3) + (lane & 7);   // B: row within 16
    const int bCol = ((lane >> 3) & 1) << 2;            // B: col sel 0/4

    float acc[2][8][4];
#pragma unroll
    for (int ct = 0; ct < 2; ct++)
#pragma unroll
        for (int dt = 0; dt < 8; dt++)
#pragma unroll
            for (int i = 0; i < 4; i++) acc[ct][dt][i] = 0.f;

    for (int it = 0; it < 4; it++) {
        const int n0 = nbase + it * 64;
        __syncthreads();
        for (int i = t; i < 8192; i += 256) {
            int c = i >> 6, n = i & 63;
            float v = g_y[((b * C + c) << 12) + n0 + n];
            uint32_t hi = f32_tf32(v);
            es[CE_FH + c * 68 + n] = hi;
            es[CE_FL + c * 68 + n] = f32_tf32(v - __uint_as_float(hi));
        }
        __syncthreads();

#pragma unroll
        for (int ks = 0; ks < 8; ks++) {
            const int k = ks * 8;
            uint32_t ah[2][4], al[2][4];
#pragma unroll
            for (int ct = 0; ct < 2; ct++) {
                uint32_t ao = (uint32_t)((cw + ct * 16 + aRow) * 68 + aCol + k);
                ldsm4(ah[ct], sbase + (CE_FH + ao) * 4);
                ldsm4(al[ct], sbase + (CE_FL + ao) * 4);
            }
#pragma unroll
            for (int p = 0; p < 4; p++) {
                uint32_t bo = (uint32_t)((dw + 16 * p + bRow) * 68 + bCol + k);
                uint32_t bh[4], bl[4];
                ldsm4(bh, sbase + (CE_FH + bo) * 4);
                ldsm4(bl, sbase + (CE_FL + bo) * 4);
#pragma unroll
                for (int ct = 0; ct < 2; ct++) {
                    mma_tf32(acc[ct][2 * p],     ah[ct], bh[0], bh[1]);
                    mma_tf32(acc[ct][2 * p],     ah[ct], bl[0], bl[1]);
                    mma_tf32(acc[ct][2 * p],     al[ct], bh[0], bh[1]);
                    mma_tf32(acc[ct][2 * p + 1], ah[ct], bh[2], bh[3]);
                    mma_tf32(acc[ct][2 * p + 1], ah[ct], bl[2], bl[3]);
                    mma_tf32(acc[ct][2 * p + 1], al[ct], bh[2], bh[3]);
                }
            }
        }
    }

    float* ep = &g_ep[(s * B + b) << 14];
#pragma unroll
    for (int ct = 0; ct < 2; ct++) {
#pragma unroll
        for (int rr = 0; rr < 2; rr++) {
            int c = cw + ct * 16 + lq + rr * 8;
#pragma unroll
            for (int dt = 0; dt < 8; dt++) {
                int d = dw + dt * 8 + lr * 2;
                float2 vv;
                vv.x = acc[ct][dt][rr * 2];
                vv.y = acc[ct][dt][rr * 2 + 1];
                *(float2*)&ep[(c << 7) + d] = vv;
            }
        }
    }
}

// ---------------- K6: CAM reduce: sum partials, attn = tanh(rowmax - e) ------
__global__ void cam_reduce_kernel() {
    const int b = blockIdx.y, c = blockIdx.x, t = threadIdx.x; // 128 threads
    float e = 0.f;
#pragma unroll
    for (int s = 0; s < ESPLIT; s++)
        e += g_ep[((s * B + b) << 14) + (c << 7) + t];
    __shared__ float red[128];
    red[t] = e;
    __syncthreads();
    for (int off = 64; off; off >>= 1) {
        if (t < off) red[t] = fmaxf(red[t], red[t + off]);
        __syncthreads();
    }
    g_e[((b * C + c) << 7) + t] = tanhf(red[0] - e);
}

// ---------------- K7: CAM out via mma.sync tf32 ------------------------------
#define CO_AS 0                        // attn tf32 [c][d] pitch 132 : 16896
#define CO_FS 16896                    // f tf32 [d][n] pitch 136    : 17408
#define CO_WORDS 34304

__global__ __launch_bounds__(256)
void cam_out_mma_kernel(const float* __restrict__ gca, float* __restrict__ out) {
    extern __shared__ uint32_t os_[];
    const int b = blockIdx.y, nb = blockIdx.x * 128;
    const int t = threadIdx.x;
    const int w = t >> 5, lane = t & 31;
    const int lq = lane >> 2, lr = lane & 3;
    const int cw = (w & 3) * 32, nw = (w >> 2) * 64;

    for (int i = t; i < 16384; i += 256) {
        int c = i >> 7, d = i & 127;
        os_[CO_AS + c * 132 + d] = f32_tf32(g_e[((b * C + c) << 7) + d]);
    }
    for (int i = t; i < 16384; i += 256) {
        int d = i >> 7, n = i & 127;
        os_[CO_FS + d * 136 + n] = f32_tf32(g_y[((b * C + d) << 12) + nb + n]);
    }
    __syncthreads();

    float acc[2][8][4];
#pragma unroll
    for (int ct = 0; ct < 2; ct++)
#pragma unroll
        for (int nt = 0; nt < 8; nt++)
#pragma unroll
            for (int i = 0; i < 4; i++) acc[ct][nt][i] = 0.f;

#pragma unroll
    for (int ks = 0; ks < 16; ks++) {
        const int k = ks * 8;
        uint32_t a[2][4];
#pragma unroll
        for (int ct = 0; ct < 2; ct++) {
            int r = (cw + ct * 16 + lq) * 132 + k + lr;
            a[ct][0] = os_[CO_AS + r];
            a[ct][1] = os_[CO_AS + r + 8 * 132];
            a[ct][2] = os_[CO_AS + r + 4];
            a[ct][3] = os_[CO_AS + r + 8 * 132 + 4];
        }
#pragma unroll
        for (int nt = 0; nt < 8; nt++) {
            uint32_t b0 = os_[CO_FS + (k + lr) * 136 + nw + nt * 8 + lq];
            uint32_t b1 = os_[CO_FS + (k + lr + 4) * 136 + nw + nt * 8 + lq];
#pragma unroll
            for (int ct = 0; ct < 2; ct++)
                mma_tf32(acc[ct][nt], a[ct], b0, b1);
        }
    }

    const float g = gca[0];
#pragma unroll
    for (int ct = 0; ct < 2; ct++) {
#pragma unroll
        for (int rr = 0; rr < 2; rr++) {
            int c = cw + ct * 16 + lq + rr * 8;
            float* row = &out[((b * C + c) << 12) + nb + nw];
#pragma unroll
            for (int nt = 0; nt < 8; nt++) {
                int n = nt * 8 + lr * 2;
                float2* p = (float2*)&row[n];
                float2 cur = *p;
                cur.x += g * acc[ct][nt][rr * 2];
                cur.y += g * acc[ct][nt][rr * 2 + 1];
                *p = cur;
            }
        }
    }
}

// ---------------- K8: PAM: m-tile 128, n-chunk 64, 3-stage cp.async ----------
// S stored UNtransposed [m][n] pitch 68 -> ldmatrix for GEMM2 A and B frags.
#define P_QS 0                       // q^T [m][qc] 128x20 = 2560
#define P_KS 2560                    // k [qc][n]  3 x 16x68 = 3264
#define P_VS 5824                    // v [c][n]   3 x 128x68 = 26112
#define P_SN 31936                   // S [m][n] 128x68 = 8704
#define P_WORDS 40640

__global__ __launch_bounds__(256, 1)
void pam_mma_kernel(const float* __restrict__ gpa, float* __restrict__ out) {
    extern __shared__ uint32_t ps[];
    const int b = blockIdx.y, m0 = blockIdx.x * 128;
    const int t = threadIdx.x;
    const int w = t >> 5, lane = t & 31;
    const int lq = lane >> 2, lr = lane & 3;
    const uint32_t sbase = (uint32_t)__cvta_generic_to_shared(ps);

    for (int i = t; i < 2048; i += 256) {
        int qc = i >> 7, m = i & 127;
        ps[P_QS + m * 20 + qc] = g_q[((b * CQK + qc) << 12) + m0 + m];
    }

    const int krow = t >> 4, kc4 = (t & 15) * 4;
    const uint32_t kdst = sbase + (P_KS + krow * 68 + kc4) * 4;
    const uint32_t* kgsrc = &g_k[((b * CQK + krow) << 12) + kc4];
    const uint32_t vdst = sbase + (P_VS + krow * 68 + kc4) * 4;
    const uint32_t* vgsrc = &g_v[((b * C + krow) << 12) + kc4];

    // prologue: chunks 0 and 1 into slots 0, 1 (separate groups)
    cp16(kdst, kgsrc);
#pragma unroll
    for (int p = 0; p < 8; p++)
        cp16(vdst + p * 16 * 68 * 4, vgsrc + (p << 16));
    cp_commit();
    cp16(kdst + 1088 * 4, kgsrc + 64);
#pragma unroll
    for (int p = 0; p < 8; p++)
        cp16(vdst + (8704 + p * 16 * 68) * 4, vgsrc + (p << 16) + 64);
    cp_commit();

    __syncthreads();   // q^T visible to all warps before fragment hoist

    uint32_t aq[2][4];
#pragma unroll
    for (int ks = 0; ks < 2; ks++) {
        int r = w * 16 + lq, c = ks * 8 + lr;
        aq[ks][0] = ps[P_QS + r * 20 + c];
        aq[ks][1] = ps[P_QS + (r + 8) * 20 + c];
        aq[ks][2] = ps[P_QS + r * 20 + c + 4];
        aq[ks][3] = ps[P_QS + (r + 8) * 20 + c + 4];
    }

    const int cw = (w & 3) * 32, mw = (w >> 2) * 64;

    // ldmatrix lane-address components
    const int aRow = lane & 15;
    const int aCol = (lane >> 4) << 2;
    const int bRow = ((lane >> 4) << 3) + (lane & 7);
    const int bCol = ((lane >> 3) & 1) << 2;
    // A (v): per-ct word offset within slot; B (S): absolute word offset
    uint32_t aOff[2], bOff[4];
#pragma unroll
    for (int ct = 0; ct < 2; ct++)
        aOff[ct] = (uint32_t)((cw + ct * 16 + aRow) * 68 + aCol);
#pragma unroll
    for (int p = 0; p < 4; p++)
        bOff[p] = (uint32_t)(P_SN + (mw + 16 * p + bRow) * 68 + bCol);

    float acc[2][8][4];
#pragma unroll
    for (int ct = 0; ct < 2; ct++)
#pragma unroll
        for (int mt = 0; mt < 8; mt++)
#pragma unroll
            for (int i = 0; i < 4; i++) acc[ct][mt][i] = 0.f;

    int sc = 0, sp = 2;    // current slot, prefetch slot ((ch+2)%3)
#pragma unroll 1
    for (int ch = 0; ch < 64; ch++) {
        cp_wait<1>();      // chunk ch landed (ch+1 may still be in flight)
        __syncthreads();   // data visibility + all warps past GEMM2(ch-1)

        // prefetch chunk ch+2 into slot sp
        if (ch + 2 < 64) {
            const int n2 = (ch + 2) * 64;
            cp16(kdst + sp * 1088 * 4, kgsrc + n2);
#pragma unroll
            for (int p = 0; p < 8; p++)
                cp16(vdst + (sp * 8704 + p * 16 * 68) * 4, vgsrc + (p << 16) + n2);
        }
        cp_commit();       // always commit to keep group count

        const uint32_t* ksb = ps + P_KS + sc * 1088;
        const uint32_t vWordBase = (uint32_t)(P_VS + sc * 8704);

        // E phase: warp rows [16w, 16w+16) x 64 n
        float e[8][4];
#pragma unroll
        for (int ni = 0; ni < 8; ni++) {
#pragma unroll
            for (int i = 0; i < 4; i++) e[ni][i] = 0.f;
#pragma unroll
            for (int ks = 0; ks < 2; ks++) {
                uint32_t b0 = ksb[(ks * 8 + lr) * 68 + ni * 8 + lq];
                uint32_t b1 = ksb[(ks * 8 + lr + 4) * 68 + ni * 8 + lq];
                mma_tf32(e[ni], aq[ks], b0, b1);
            }
        }
        // tanh -> S[m][n] (paired 64-bit stores)
        {
            int m = w * 16 + lq;
#pragma unroll
            for (int ni = 0; ni < 8; ni++) {
                int n = ni * 8 + lr * 2;
                uint2 u0, u1;
                u0.x = f32_tf32(tanh_ap(e[ni][0]));
                u0.y = f32_tf32(tanh_ap(e[ni][1]));
                u1.x = f32_tf32(tanh_ap(e[ni][2]));
                u1.y = f32_tf32(tanh_ap(e[ni][3]));
                *(uint2*)&ps[P_SN + m * 68 + n]       = u0;
                *(uint2*)&ps[P_SN + (m + 8) * 68 + n] = u1;
            }
        }
        __syncthreads();   // S exchange

        // GEMM2: acc[32c x 64m] += v * S^T  (ldmatrix frags)
#pragma unroll
        for (int ks = 0; ks < 8; ks++) {
            const int k = ks * 8;
            uint32_t a[2][4], bb8[4][4];
#pragma unroll
            for (int ct = 0; ct < 2; ct++)
                ldsm4(a[ct], sbase + (vWordBase + aOff[ct] + k) * 4);
#pragma unroll
            for (int p = 0; p < 4; p++)
                ldsm4(bb8[p], sbase + (bOff[p] + k) * 4);
#pragma unroll
            for (int ct = 0; ct < 2; ct++)
#pragma unroll
                for (int mt = 0; mt < 8; mt++)
                    mma_tf32(acc[ct][mt], a[ct], bb8[mt >> 1][(mt & 1) * 2],
                             bb8[mt >> 1][(mt & 1) * 2 + 1]);
        }

        sc = (sc == 2) ? 0 : sc + 1;
        sp = (sp == 2) ? 0 : sp + 1;
    }

    const float g = gpa[0];
#pragma unroll
    for (int ct = 0; ct < 2; ct++) {
#pragma unroll
        for (int rr = 0; rr < 2; rr++) {
            int c = cw + ct * 16 + lq + rr * 8;
            float* row = &out[((b * C + c) << 12) + m0 + mw];
#pragma unroll
            for (int mt = 0; mt < 8; mt++) {
                int m = mt * 8 + lr * 2;
                float2* p = (float2*)&row[m];
                float2 cur = *p;
                cur.x += g * acc[ct][mt][rr * 2];
                cur.y += g * acc[ct][mt][rr * 2 + 1];
                *p = cur;
            }
        }
    }
}

// ---------------- launch ----------------
extern "C" void kernel_launch(void* const* d_in, const int* in_sizes, int n_in,
                              void* d_out, int out_size) {
    const float* x       = (const float*)d_in[0];
    const float* conv_w  = (const float*)d_in[1];
    const float* bn_g    = (const float*)d_in[2];
    const float* bn_b    = (const float*)d_in[3];
    const float* q_w     = (const float*)d_in[4];
    const float* q_b     = (const float*)d_in[5];
    const float* k_w     = (const float*)d_in[6];
    const float* k_b     = (const float*)d_in[7];
    const float* v_w     = (const float*)d_in[8];
    const float* v_b     = (const float*)d_in[9];
    const float* gca     = (const float*)d_in[10];
    const float* gpa     = (const float*)d_in[11];
    float* out = (float*)d_out;

    cudaFuncSetAttribute(conv_tc_kernel, cudaFuncAttributeMaxDynamicSharedMemorySize,
                         CONV_SMEM_WORDS * 4);
    cudaFuncSetAttribute(pam_mma_kernel, cudaFuncAttributeMaxDynamicSharedMemorySize,
                         P_WORDS * 4);
    cudaFuncSetAttribute(qkv_mma_kernel, cudaFuncAttributeMaxDynamicSharedMemorySize,
                         QK_WORDS * 4);
    cudaFuncSetAttribute(cam_energy_mma_kernel, cudaFuncAttributeMaxDynamicSharedMemorySize,
                         CE_WORDS * 4);
    cudaFuncSetAttribute(cam_out_mma_kernel, cudaFuncAttributeMaxDynamicSharedMemorySize,
                         CO_WORDS * 4);

    wprep_kernel<<<1152, 256>>>(conv_w);
    conv_tc_kernel<<<dim3(64, B), 256, CONV_SMEM_WORDS * 4>>>(x);
    bnstats1_kernel<<<512, 256>>>();
    bnstats2_kernel<<<1, 128>>>(bn_g, bn_b);
    bnrelu_kernel<<<2048, 256>>>(out);
    qkv_mma_kernel<<<dim3(64, B), 320, QK_WORDS * 4>>>(q_w, q_b, k_w, k_b, v_w, v_b);
    cam_energy_mma_kernel<<<dim3(ESPLIT, B), 256, CE_WORDS * 4>>>();
    cam_reduce_kernel<<<dim3(C, B), 128>>>();
    cam_out_mma_kernel<<<dim3(32, B), 256, CO_WORDS * 4>>>(gca, out);
    pam_mma_kernel<<<dim3(32, B), 256, P_WORDS * 4>>>(gpa, out);
}

// round 12
// speedup vs baseline: 1.0669x; 1.0669x over previous
#include <cuda_runtime.h>
#include <math.h>
#include <stdint.h>

// Problem constants
#define B   4
#define CIN 256
#define C   128
#define HW  64
#define N   4096          // HW*HW
#define CQK 16
#define ESPLIT 16         // CAM energy split-k slices

// ---------------- scratch (device globals; no allocation) ----------------
__device__ float g_y[B * C * N];        // conv out, then feat (in-place) : 8 MB
__device__ float g_scale[C];
__device__ float g_shift[C];
__device__ float g_bnp0[512];
__device__ float g_bnp1[512];
__device__ uint32_t g_q[B * CQK * N];   // tf32 bits
__device__ uint32_t g_k[B * CQK * N];   // tf32 bits
__device__ uint32_t g_v[B * C * N];     // tf32 bits : 8 MB
__device__ float g_e[B * C * C];        // CAM attn
__device__ float g_ep[ESPLIT * B * C * C];  // CAM energy partials : 4 MB
__device__ uint32_t g_w2hi[9 * 128 * 256];  // conv weights, tf32 hi, [off][co][ci]
__device__ uint32_t g_w2lo[9 * 128 * 256];  // tf32 residual

// ================= base-ISA tensor helpers (NO tcgen05 — plain sm_103) ======
__device__ __forceinline__ uint32_t f32_tf32(float f) {
    uint32_t r;
    asm("cvt.rna.tf32.f32 %0, %1;" : "=r"(r) : "f"(f));
    return r;
}
__device__ __forceinline__ float tanh_ap(float x) {
    float y;
    asm("tanh.approx.f32 %0, %1;" : "=f"(y) : "f"(x));
    return y;
}
__device__ __forceinline__ void red_add(float* p, float v) {
    asm volatile("red.global.add.f32 [%0], %1;" :: "l"(p), "f"(v) : "memory");
}
// D += A(16x8 tf32) * B(8x8 tf32), fp32 accum
__device__ __forceinline__ void mma_tf32(float* d, const uint32_t* a, uint32_t b0, uint32_t b1) {
    asm volatile(
        "mma.sync.aligned.m16n8k8.row.col.f32.tf32.tf32.f32 "
        "{%0,%1,%2,%3}, {%4,%5,%6,%7}, {%8,%9}, {%0,%1,%2,%3};"
        : "+f"(d[0]), "+f"(d[1]), "+f"(d[2]), "+f"(d[3])
        : "r"(a[0]), "r"(a[1]), "r"(a[2]), "r"(a[3]), "r"(b0), "r"(b1));
}
// ldmatrix x4 (b16 view; loads 4 8x4-b32 matrices)
__device__ __forceinline__ void ldsm4(uint32_t* r, uint32_t saddr) {
    asm volatile("ldmatrix.sync.aligned.m8n8.x4.shared.b16 {%0,%1,%2,%3}, [%4];"
                 : "=r"(r[0]), "=r"(r[1]), "=r"(r[2]), "=r"(r[3]) : "r"(saddr));
}
__device__ __forceinline__ void cp16(uint32_t saddr, const void* g) {
    asm volatile("cp.async.cg.shared.global [%0], [%1], 16;" :: "r"(saddr), "l"(g));
}
__device__ __forceinline__ void cp_commit() {
    asm volatile("cp.async.commit_group;" ::: "memory");
}
template <int NN> __device__ __forceinline__ void cp_wait() {
    asm volatile("cp.async.wait_group %0;" :: "n"(NN) : "memory");
}

// ---------------- K0: weight prep: w -> tf32 hi/lo, [off][co][ci] ------------
__global__ void wprep_kernel(const float* __restrict__ w) {
    int i = blockIdx.x * 256 + threadIdx.x;
    if (i >= 9 * 128 * 256) return;
    int off = i >> 15;
    int rem = i & 32767;
    int co = rem >> 8, ci = rem & 255;
    float v = w[(co * 256 + ci) * 9 + off];
    uint32_t hi = f32_tf32(v);
    g_w2hi[i] = hi;
    g_w2lo[i] = f32_tf32(v - __uint_as_float(hi));
}

// ---------------- K1: 3x3 conv via mma.sync tf32 (3xTF32 split) --------------
#define XS_HI 0
#define XS_LO 6400
#define WS_HI 12800
#define WS_LO 17408
#define CONV_SMEM_WORDS 22016

__global__ __launch_bounds__(256)
void conv_tc_kernel(const float* __restrict__ x) {
    extern __shared__ uint32_t cs[];
    const int y = blockIdx.x, b = blockIdx.y;
    const int t = threadIdx.x;
    const int w = t >> 5, lane = t & 31;
    const int lq = lane >> 2, lr = lane & 3;
    const int cw = (w >> 1) * 32;
    const int pw = (w & 1) * 32;

    float acc[2][4][4];
#pragma unroll
    for (int ct = 0; ct < 2; ct++)
#pragma unroll
        for (int nt = 0; nt < 4; nt++)
#pragma unroll
            for (int i = 0; i < 4; i++) acc[ct][nt][i] = 0.f;

    for (int ci0 = 0; ci0 < CIN; ci0 += 32) {
        __syncthreads();
        for (int i = t; i < 32 * 198; i += 256) {
            int ci = i / 198, rem = i % 198;
            int yy = rem / 66, xx = rem % 66;
            int gy = y + yy - 1, gx = xx - 1;
            float v = 0.f;
            if (gy >= 0 && gy < HW && gx >= 0 && gx < HW)
                v = x[(((b * CIN + ci0 + ci) << 6) + gy) * 64 + gx];
            uint32_t hi = f32_tf32(v);
            int a = ci * 200 + yy * 66 + xx;
            cs[XS_HI + a] = hi;
            cs[XS_LO + a] = f32_tf32(v - __uint_as_float(hi));
        }

#pragma unroll 1
        for (int off = 0; off < 9; off++) {
            __syncthreads();
            {
                int base = (off << 15) + ci0;
#pragma unroll
                for (int p = 0; p < 16; p++) {
                    int i = t + p * 256;
                    int co = i >> 5, ci = i & 31;
                    int src = base + (co << 8) + ci;
                    cs[WS_HI + co * 36 + ci] = g_w2hi[src];
                    cs[WS_LO + co * 36 + ci] = g_w2lo[src];
                }
            }
            __syncthreads();
            const int ky = off / 3, kx = off % 3;
            const int xbase = ky * 66 + kx + pw;

#pragma unroll
            for (int ks = 0; ks < 4; ks++) {
                int k = ks * 8;
                uint32_t ahi[2][4], alo[2][4];
#pragma unroll
                for (int ct = 0; ct < 2; ct++) {
                    int r = (cw + ct * 16 + lq) * 36 + k + lr;
                    ahi[ct][0] = cs[WS_HI + r];
                    ahi[ct][1] = cs[WS_HI + r + 8 * 36];
                    ahi[ct][2] = cs[WS_HI + r + 4];
                    ahi[ct][3] = cs[WS_HI + r + 8 * 36 + 4];
                    alo[ct][0] = cs[WS_LO + r];
                    alo[ct][1] = cs[WS_LO + r + 8 * 36];
                    alo[ct][2] = cs[WS_LO + r + 4];
                    alo[ct][3] = cs[WS_LO + r + 8 * 36 + 4];
                }
#pragma unroll
                for (int nt = 0; nt < 4; nt++) {
                    int a0 = (k + lr) * 200 + xbase + nt * 8 + lq;
                    int a1 = a0 + 4 * 200;
                    uint32_t bh0 = cs[XS_HI + a0], bh1 = cs[XS_HI + a1];
                    uint32_t bl0 = cs[XS_LO + a0], bl1 = cs[XS_LO + a1];
#pragma unroll
                    for (int ct = 0; ct < 2; ct++) {
                        mma_tf32(acc[ct][nt], ahi[ct], bh0, bh1);
                        mma_tf32(acc[ct][nt], ahi[ct], bl0, bl1);
                        mma_tf32(acc[ct][nt], alo[ct], bh0, bh1);
                    }
                }
            }
        }
    }

#pragma unroll
    for (int ct = 0; ct < 2; ct++) {
#pragma unroll
        for (int rr = 0; rr < 2; rr++) {
            int co = cw + ct * 16 + lq + rr * 8;
            float* row = &g_y[((b * C + co) << 12) + (y << 6) + pw];
#pragma unroll
            for (int nt = 0; nt < 4; nt++) {
                int m = nt * 8 + lr * 2;
                float2 vv;
                vv.x = acc[ct][nt][rr * 2];
                vv.y = acc[ct][nt][rr * 2 + 1];
                *(float2*)&row[m] = vv;
            }
        }
    }
}

// ---------------- K2a: per-(channel,batch) partial stats ----------------
__global__ void bnstats1_kernel() {
    const int blk = blockIdx.x;            // 512 = c*4 + b
    const int c = blk >> 2, b = blk & 3;
    const int t = threadIdx.x;
    const float4* p = (const float4*)&g_y[(b * C + c) << 12];
    float s = 0.f, ss = 0.f;
#pragma unroll
    for (int i = 0; i < 4; i++) {
        float4 v = p[t + i * 256];
        s += v.x + v.y + v.z + v.w;
        ss += v.x * v.x + v.y * v.y + v.z * v.z + v.w * v.w;
    }
    __shared__ float r1[256], r2[256];
    r1[t] = s; r2[t] = ss;
    __syncthreads();
    for (int off = 128; off; off >>= 1) {
        if (t < off) { r1[t] += r1[t + off]; r2[t] += r2[t + off]; }
        __syncthreads();
    }
    if (t == 0) { g_bnp0[blk] = r1[0]; g_bnp1[blk] = r2[0]; }
}

// ---------------- K2b: finalize scale/shift ----------------
__global__ void bnstats2_kernel(const float* __restrict__ gamma, const float* __restrict__ beta) {
    const int c = threadIdx.x;             // 128
    float s = 0.f, ss = 0.f;
#pragma unroll
    for (int b = 0; b < 4; b++) { s += g_bnp0[c * 4 + b]; ss += g_bnp1[c * 4 + b]; }
    const float inv = 1.f / (float)(B * N);
    float mean = s * inv;
    float var  = ss * inv - mean * mean;
    float istd = rsqrtf(var + 1e-5f);
    float sc = gamma[c] * istd;
    g_scale[c] = sc;
    g_shift[c] = beta[c] - mean * sc;
}

// ---------------- K3: BN + ReLU, d_out = 3*feat ----------------
__global__ void bnrelu_kernel(float* __restrict__ out) {
    const int total = B * C * N;
    for (int i = blockIdx.x * 256 + threadIdx.x; i < total; i += 2048 * 256) {
        int c = (i >> 12) & (C - 1);
        float v = fmaxf(g_y[i] * g_scale[c] + g_shift[c], 0.f);
        g_y[i] = v;
        out[i] = 3.f * v;
    }
}

// ---------------- K4: qkv via mma.sync tf32 ----------------------------------
#define QK_WS 0
#define QK_FS 21120
#define QK_BIAS 30336
#define QK_WORDS 30496

__global__ __launch_bounds__(320)
void qkv_mma_kernel(const float* __restrict__ qw, const float* __restrict__ qb,
                    const float* __restrict__ kw, const float* __restrict__ kb,
                    const float* __restrict__ vw, const float* __restrict__ vb) {
    extern __shared__ uint32_t qs_[];
    const int b = blockIdx.y, n0 = blockIdx.x * 64;
    const int t = threadIdx.x;
    const int w = t >> 5, lane = t & 31;
    const int lq = lane >> 2, lr = lane & 3;

    for (int i = t; i < 160 * 128; i += 320) {
        int o = i >> 7, c = i & 127;
        float wv = (o < 16) ? qw[o * C + c]
                 : (o < 32) ? kw[(o - 16) * C + c]
                            : vw[(o - 32) * C + c];
        qs_[QK_WS + o * 132 + c] = f32_tf32(wv);
    }
    if (t < 160)
        ((float*)(qs_ + QK_BIAS))[t] = (t < 16) ? qb[t] : (t < 32 ? kb[t - 16] : vb[t - 32]);
    for (int i = t; i < 8192; i += 320) {
        int c = i >> 6, n = i & 63;
        qs_[QK_FS + c * 72 + n] = f32_tf32(g_y[((b * C + c) << 12) + n0 + n]);
    }
    __syncthreads();

    const int o0 = w * 16;
    float acc[8][4];
#pragma unroll
    for (int nt = 0; nt < 8; nt++)
#pragma unroll
        for (int i = 0; i < 4; i++) acc[nt][i] = 0.f;

#pragma unroll
    for (int ks = 0; ks < 16; ks++) {
        const int k = ks * 8;
        uint32_t a[4];
        {
            int r = (o0 + lq) * 132 + k + lr;
            a[0] = qs_[QK_WS + r];
            a[1] = qs_[QK_WS + r + 8 * 132];
            a[2] = qs_[QK_WS + r + 4];
            a[3] = qs_[QK_WS + r + 8 * 132 + 4];
        }
#pragma unroll
        for (int nt = 0; nt < 8; nt++) {
            uint32_t b0 = qs_[QK_FS + (k + lr) * 72 + nt * 8 + lq];
            uint32_t b1 = qs_[QK_FS + (k + lr + 4) * 72 + nt * 8 + lq];
            mma_tf32(acc[nt], a, b0, b1);
        }
    }

    const float* bias = (const float*)(qs_ + QK_BIAS);
#pragma unroll
    for (int rr = 0; rr < 2; rr++) {
        int o = o0 + lq + rr * 8;
        float bi = bias[o];
        uint32_t* dst = (o < 16) ? &g_q[((b * CQK + o) << 12) + n0]
                      : (o < 32) ? &g_k[((b * CQK + o - 16) << 12) + n0]
                                 : &g_v[((b * C + o - 32) << 12) + n0];
#pragma unroll
        for (int nt = 0; nt < 8; nt++) {
            int n = nt * 8 + lr * 2;
            uint2 u;
            u.x = f32_tf32(acc[nt][rr * 2] + bi);
            u.y = f32_tf32(acc[nt][rr * 2 + 1] + bi);
            *(uint2*)&dst[n] = u;
        }
    }
}

// ---------------- K5: CAM energy via mma.sync tf32, 3x split, split-k --------
#define CE_FH 0
#define CE_FL 8704
#define CE_WORDS 17408

__global__ __launch_bounds__(256)
void cam_energy_mma_kernel() {
    extern __shared__ uint32_t es[];
    const int b = blockIdx.y, s = blockIdx.x;
    const int nbase = s * (N / ESPLIT);
    const int t = threadIdx.x;
    const int w = t >> 5, lane = t & 31;
    const int lq = lane >> 2, lr = lane & 3;
    const int cw = (w & 3) * 32, dw = (w >> 2) * 64;
    const uint32_t sbase = (uint32_t)__cvta_generic_to_shared(es);

    const int aRow = lane & 15;
    const int aCol = (lane >> 4) << 2;
    const int bRow = ((lane >> 4) << 3) + (lane & 7);
    const int bCol = ((lane >> 3) & 1) << 2;

    float acc[2][8][4];
#pragma unroll
    for (int ct = 0; ct < 2; ct++)
#pragma unroll
        for (int dt = 0; dt < 8; dt++)
#pragma unroll
            for (int i = 0; i < 4; i++) acc[ct][dt][i] = 0.f;

    for (int it = 0; it < 4; it++) {
        const int n0 = nbase + it * 64;
        __syncthreads();
        for (int i = t; i < 8192; i += 256) {
            int c = i >> 6, n = i & 63;
            float v = g_y[((b * C + c) << 12) + n0 + n];
            uint32_t hi = f32_tf32(v);
            es[CE_FH + c * 68 + n] = hi;
            es[CE_FL + c * 68 + n] = f32_tf32(v - __uint_as_float(hi));
        }
        __syncthreads();

#pragma unroll
        for (int ks = 0; ks < 8; ks++) {
            const int k = ks * 8;
            uint32_t ah[2][4], al[2][4];
#pragma unroll
            for (int ct = 0; ct < 2; ct++) {
                uint32_t ao = (uint32_t)((cw + ct * 16 + aRow) * 68 + aCol + k);
                ldsm4(ah[ct], sbase + (CE_FH + ao) * 4);
                ldsm4(al[ct], sbase + (CE_FL + ao) * 4);
            }
#pragma unroll
            for (int p = 0; p < 4; p++) {
                uint32_t bo = (uint32_t)((dw + 16 * p + bRow) * 68 + bCol + k);
                uint32_t bh[4], bl[4];
                ldsm4(bh, sbase + (CE_FH + bo) * 4);
                ldsm4(bl, sbase + (CE_FL + bo) * 4);
#pragma unroll
                for (int ct = 0; ct < 2; ct++) {
                    mma_tf32(acc[ct][2 * p],     ah[ct], bh[0], bh[1]);
                    mma_tf32(acc[ct][2 * p],     ah[ct], bl[0], bl[1]);
                    mma_tf32(acc[ct][2 * p],     al[ct], bh[0], bh[1]);
                    mma_tf32(acc[ct][2 * p + 1], ah[ct], bh[2], bh[3]);
                    mma_tf32(acc[ct][2 * p + 1], ah[ct], bl[2], bl[3]);
                    mma_tf32(acc[ct][2 * p + 1], al[ct], bh[2], bh[3]);
                }
            }
        }
    }

    float* ep = &g_ep[(s * B + b) << 14];
#pragma unroll
    for (int ct = 0; ct < 2; ct++) {
#pragma unroll
        for (int rr = 0; rr < 2; rr++) {
            int c = cw + ct * 16 + lq + rr * 8;
#pragma unroll
            for (int dt = 0; dt < 8; dt++) {
                int d = dw + dt * 8 + lr * 2;
                float2 vv;
                vv.x = acc[ct][dt][rr * 2];
                vv.y = acc[ct][dt][rr * 2 + 1];
                *(float2*)&ep[(c << 7) + d] = vv;
            }
        }
    }
}

// ---------------- K6: CAM reduce: sum partials, attn = tanh(rowmax - e) ------
__global__ void cam_reduce_kernel() {
    const int b = blockIdx.y, c = blockIdx.x, t = threadIdx.x; // 128 threads
    float e = 0.f;
#pragma unroll
    for (int s = 0; s < ESPLIT; s++)
        e += g_ep[((s * B + b) << 14) + (c << 7) + t];
    __shared__ float red[128];
    red[t] = e;
    __syncthreads();
    for (int off = 64; off; off >>= 1) {
        if (t < off) red[t] = fmaxf(red[t], red[t + off]);
        __syncthreads();
    }
    g_e[((b * C + c) << 7) + t] = tanhf(red[0] - e);
}

// ---------------- K7: CAM out via mma.sync tf32 (atomic out += ) -------------
#define CO_AS 0
#define CO_FS 16896
#define CO_WORDS 34304

__global__ __launch_bounds__(256)
void cam_out_mma_kernel(const float* __restrict__ gca, float* __restrict__ out) {
    extern __shared__ uint32_t os_[];
    const int b = blockIdx.y, nb = blockIdx.x * 128;
    const int t = threadIdx.x;
    const int w = t >> 5, lane = t & 31;
    const int lq = lane >> 2, lr = lane & 3;
    const int cw = (w & 3) * 32, nw = (w >> 2) * 64;

    for (int i = t; i < 16384; i += 256) {
        int c = i >> 7, d = i & 127;
        os_[CO_AS + c * 132 + d] = f32_tf32(g_e[((b * C + c) << 7) + d]);
    }
    for (int i = t; i < 16384; i += 256) {
        int d = i >> 7, n = i & 127;
        os_[CO_FS + d * 136 + n] = f32_tf32(g_y[((b * C + d) << 12) + nb + n]);
    }
    __syncthreads();

    float acc[2][8][4];
#pragma unroll
    for (int ct = 0; ct < 2; ct++)
#pragma unroll
        for (int nt = 0; nt < 8; nt++)
#pragma unroll
            for (int i = 0; i < 4; i++) acc[ct][nt][i] = 0.f;

#pragma unroll
    for (int ks = 0; ks < 16; ks++) {
        const int k = ks * 8;
        uint32_t a[2][4];
#pragma unroll
        for (int ct = 0; ct < 2; ct++) {
            int r = (cw + ct * 16 + lq) * 132 + k + lr;
            a[ct][0] = os_[CO_AS + r];
            a[ct][1] = os_[CO_AS + r + 8 * 132];
            a[ct][2] = os_[CO_AS + r + 4];
            a[ct][3] = os_[CO_AS + r + 8 * 132 + 4];
        }
#pragma unroll
        for (int nt = 0; nt < 8; nt++) {
            uint32_t b0 = os_[CO_FS + (k + lr) * 136 + nw + nt * 8 + lq];
            uint32_t b1 = os_[CO_FS + (k + lr + 4) * 136 + nw + nt * 8 + lq];
#pragma unroll
            for (int ct = 0; ct < 2; ct++)
                mma_tf32(acc[ct][nt], a[ct], b0, b1);
        }
    }

    const float g = gca[0];
#pragma unroll
    for (int ct = 0; ct < 2; ct++) {
#pragma unroll
        for (int rr = 0; rr < 2; rr++) {
            int c = cw + ct * 16 + lq + rr * 8;
            float* row = &out[((b * C + c) << 12) + nb + nw];
#pragma unroll
            for (int nt = 0; nt < 8; nt++) {
                int n = nt * 8 + lr * 2;
                red_add(&row[n],     g * acc[ct][nt][rr * 2]);
                red_add(&row[n + 1], g * acc[ct][nt][rr * 2 + 1]);
            }
        }
    }
}

// ---------------- K8: PAM: m-tile 128, n-chunk 64, 3-stage cp.async ----------
#define P_QS 0
#define P_KS 2560
#define P_VS 5824
#define P_SN 31936
#define P_WORDS 40640

__global__ __launch_bounds__(256, 1)
void pam_mma_kernel(const float* __restrict__ gpa, float* __restrict__ out) {
    extern __shared__ uint32_t ps[];
    const int b = blockIdx.y, m0 = blockIdx.x * 128;
    const int t = threadIdx.x;
    const int w = t >> 5, lane = t & 31;
    const int lq = lane >> 2, lr = lane & 3;
    const uint32_t sbase = (uint32_t)__cvta_generic_to_shared(ps);

    for (int i = t; i < 2048; i += 256) {
        int qc = i >> 7, m = i & 127;
        ps[P_QS + m * 20 + qc] = g_q[((b * CQK + qc) << 12) + m0 + m];
    }

    const int krow = t >> 4, kc4 = (t & 15) * 4;
    const uint32_t kdst = sbase + (P_KS + krow * 68 + kc4) * 4;
    const uint32_t* kgsrc = &g_k[((b * CQK + krow) << 12) + kc4];
    const uint32_t vdst = sbase + (P_VS + krow * 68 + kc4) * 4;
    const uint32_t* vgsrc = &g_v[((b * C + krow) << 12) + kc4];

    cp16(kdst, kgsrc);
#pragma unroll
    for (int p = 0; p < 8; p++)
        cp16(vdst + p * 16 * 68 * 4, vgsrc + (p << 16));
    cp_commit();
    cp16(kdst + 1088 * 4, kgsrc + 64);
#pragma unroll
    for (int p = 0; p < 8; p++)
        cp16(vdst + (8704 + p * 16 * 68) * 4, vgsrc + (p << 16) + 64);
    cp_commit();

    __syncthreads();

    uint32_t aq[2][4];
#pragma unroll
    for (int ks = 0; ks < 2; ks++) {
        int r = w * 16 + lq, c = ks * 8 + lr;
        aq[ks][0] = ps[P_QS + r * 20 + c];
        aq[ks][1] = ps[P_QS + (r + 8) * 20 + c];
        aq[ks][2] = ps[P_QS + r * 20 + c + 4];
        aq[ks][3] = ps[P_QS + (r + 8) * 20 + c + 4];
    }

    const int cw = (w & 3) * 32, mw = (w >> 2) * 64;

    const int aRow = lane & 15;
    const int aCol = (lane >> 4) << 2;
    const int bRow = ((lane >> 4) << 3) + (lane & 7);
    const int bCol = ((lane >> 3) & 1) << 2;
    uint32_t aOff[2], bOff[4];
#pragma unroll
    for (int ct = 0; ct < 2; ct++)
        aOff[ct] = (uint32_t)((cw + ct * 16 + aRow) * 68 + aCol);
#pragma unroll
    for (int p = 0; p < 4; p++)
        bOff[p] = (uint32_t)(P_SN + (mw + 16 * p + bRow) * 68 + bCol);

    float acc[2][8][4];
#pragma unroll
    for (int ct = 0; ct < 2; ct++)
#pragma unroll
        for (int mt = 0; mt < 8; mt++)
#pragma unroll
            for (int i = 0; i < 4; i++) acc[ct][mt][i] = 0.f;

    int sc = 0, sp = 2;
#pragma unroll 1
    for (int ch = 0; ch < 64; ch++) {
        cp_wait<1>();
        __syncthreads();

        if (ch + 2 < 64) {
            const int n2 = (ch + 2) * 64;
            cp16(kdst + sp * 1088 * 4, kgsrc + n2);
#pragma unroll
            for (int p = 0; p < 8; p++)
                cp16(vdst + (sp * 8704 + p * 16 * 68) * 4, vgsrc + (p << 16) + n2);
        }
        cp_commit();

        const uint32_t* ksb = ps + P_KS + sc * 1088;
        const uint32_t vWordBase = (uint32_t)(P_VS + sc * 8704);

        float e[8][4];
#pragma unroll
        for (int ni = 0; ni < 8; ni++) {
#pragma unroll
            for (int i = 0; i < 4; i++) e[ni][i] = 0.f;
#pragma unroll
            for (int ks = 0; ks < 2; ks++) {
                uint32_t b0 = ksb[(ks * 8 + lr) * 68 + ni * 8 + lq];
                uint32_t b1 = ksb[(ks * 8 + lr + 4) * 68 + ni * 8 + lq];
                mma_tf32(e[ni], aq[ks], b0, b1);
            }
        }
        {
            int m = w * 16 + lq;
#pragma unroll
            for (int ni = 0; ni < 8; ni++) {
                int n = ni * 8 + lr * 2;
                uint2 u0, u1;
                u0.x = f32_tf32(tanh_ap(e[ni][0]));
                u0.y = f32_tf32(tanh_ap(e[ni][1]));
                u1.x = f32_tf32(tanh_ap(e[ni][2]));
                u1.y = f32_tf32(tanh_ap(e[ni][3]));
                *(uint2*)&ps[P_SN + m * 68 + n]       = u0;
                *(uint2*)&ps[P_SN + (m + 8) * 68 + n] = u1;
            }
        }
        __syncthreads();

#pragma unroll
        for (int ks = 0; ks < 8; ks++) {
            const int k = ks * 8;
            uint32_t a[2][4], bb8[4][4];
#pragma unroll
            for (int ct = 0; ct < 2; ct++)
                ldsm4(a[ct], sbase + (vWordBase + aOff[ct] + k) * 4);
#pragma unroll
            for (int p = 0; p < 4; p++)
                ldsm4(bb8[p], sbase + (bOff[p] + k) * 4);
#pragma unroll
            for (int ct = 0; ct < 2; ct++)
#pragma unroll
                for (int mt = 0; mt < 8; mt++)
                    mma_tf32(acc[ct][mt], a[ct], bb8[mt >> 1][(mt & 1) * 2],
                             bb8[mt >> 1][(mt & 1) * 2 + 1]);
        }

        sc = (sc == 2) ? 0 : sc + 1;
        sp = (sp == 2) ? 0 : sp + 1;
    }

    const float g = gpa[0];
#pragma unroll
    for (int ct = 0; ct < 2; ct++) {
#pragma unroll
        for (int rr = 0; rr < 2; rr++) {
            int c = cw + ct * 16 + lq + rr * 8;
            float* row = &out[((b * C + c) << 12) + m0 + mw];
#pragma unroll
            for (int mt = 0; mt < 8; mt++) {
                int m = mt * 8 + lr * 2;
                red_add(&row[m],     g * acc[ct][mt][rr * 2]);
                red_add(&row[m + 1], g * acc[ct][mt][rr * 2 + 1]);
            }
        }
    }
}

// ---------------- launch (forked streams: CAM chain || qkv+PAM) --------------
extern "C" void kernel_launch(void* const* d_in, const int* in_sizes, int n_in,
                              void* d_out, int out_size) {
    const float* x       = (const float*)d_in[0];
    const float* conv_w  = (const float*)d_in[1];
    const float* bn_g    = (const float*)d_in[2];
    const float* bn_b    = (const float*)d_in[3];
    const float* q_w     = (const float*)d_in[4];
    const float* q_b     = (const float*)d_in[5];
    const float* k_w     = (const float*)d_in[6];
    const float* k_b     = (const float*)d_in[7];
    const float* v_w     = (const float*)d_in[8];
    const float* v_b     = (const float*)d_in[9];
    const float* gca     = (const float*)d_in[10];
    const float* gpa     = (const float*)d_in[11];
    float* out = (float*)d_out;

    static cudaStream_t sA = nullptr, sB = nullptr;
    static cudaEvent_t ev0 = nullptr, evA = nullptr, evB = nullptr;
    if (!sA) {
        cudaStreamCreateWithFlags(&sA, cudaStreamNonBlocking);
        cudaStreamCreateWithFlags(&sB, cudaStreamNonBlocking);
        cudaEventCreateWithFlags(&ev0, cudaEventDisableTiming);
        cudaEventCreateWithFlags(&evA, cudaEventDisableTiming);
        cudaEventCreateWithFlags(&evB, cudaEventDisableTiming);

        cudaFuncSetAttribute(conv_tc_kernel, cudaFuncAttributeMaxDynamicSharedMemorySize,
                             CONV_SMEM_WORDS * 4);
        cudaFuncSetAttribute(pam_mma_kernel, cudaFuncAttributeMaxDynamicSharedMemorySize,
                             P_WORDS * 4);
        cudaFuncSetAttribute(qkv_mma_kernel, cudaFuncAttributeMaxDynamicSharedMemorySize,
                             QK_WORDS * 4);
        cudaFuncSetAttribute(cam_energy_mma_kernel, cudaFuncAttributeMaxDynamicSharedMemorySize,
                             CE_WORDS * 4);
        cudaFuncSetAttribute(cam_out_mma_kernel, cudaFuncAttributeMaxDynamicSharedMemorySize,
                             CO_WORDS * 4);
    }

    // serial prologue on the launch stream
    wprep_kernel<<<1152, 256>>>(conv_w);
    conv_tc_kernel<<<dim3(64, B), 256, CONV_SMEM_WORDS * 4>>>(x);
    bnstats1_kernel<<<512, 256>>>();
    bnstats2_kernel<<<1, 128>>>(bn_g, bn_b);
    bnrelu_kernel<<<2048, 256>>>(out);

    // fork
    cudaEventRecord(ev0, 0);
    cudaStreamWaitEvent(sA, ev0, 0);
    cudaStreamWaitEvent(sB, ev0, 0);

    // stream A: CAM chain (atomic adds into out)
    cam_energy_mma_kernel<<<dim3(ESPLIT, B), 256, CE_WORDS * 4, sA>>>();
    cam_reduce_kernel<<<dim3(C, B), 128, 0, sA>>>();
    cam_out_mma_kernel<<<dim3(32, B), 256, CO_WORDS * 4, sA>>>(gca, out);

    // stream B: qkv -> PAM (atomic adds into out)
    qkv_mma_kernel<<<dim3(64, B), 320, QK_WORDS * 4, sB>>>(q_w, q_b, k_w, k_b, v_w, v_b);
    pam_mma_kernel<<<dim3(32, B), 256, P_WORDS * 4, sB>>>(gpa, out);

    // join
    cudaEventRecord(evA, sA);
    cudaEventRecord(evB, sB);
    cudaStreamWaitEvent(0, evA, 0);
    cudaStreamWaitEvent(0, evB, 0);
}

// round 13
// speedup vs baseline: 1.3022x; 1.2206x over previous
#include <cuda_runtime.h>
#include <cuda_bf16.h>
#include <math.h>
#include <stdint.h>

// Problem constants
#define B   4
#define CIN 256
#define C   128
#define HW  64
#define N   4096          // HW*HW
#define CQK 16
#define ESPLIT 16         // CAM energy split-k slices

// ---------------- scratch (device globals; no allocation) ----------------
__device__ float g_y[B * C * N];        // conv out, then feat (in-place) : 8 MB
__device__ float g_bnp0[512];
__device__ float g_bnp1[512];
__device__ uint32_t g_q[B * CQK * N];   // tf32 bits
__device__ uint32_t g_k[B * CQK * N];   // tf32 bits
__device__ uint32_t g_v[B * C * N];     // tf32 bits : 8 MB
__device__ float g_e[B * C * C];        // CAM attn
__device__ float g_ep[ESPLIT * B * C * C];  // CAM energy partials : 4 MB
__device__ uint32_t g_w2hi[9 * 128 * 128];  // conv w, bf16x2 hi pairs [off][co][ci/2]
__device__ uint32_t g_w2lo[9 * 128 * 128];  // bf16x2 residual pairs

// ================= base-ISA tensor helpers (NO tcgen05 — plain sm_103) ======
__device__ __forceinline__ uint32_t f32_tf32(float f) {
    uint32_t r;
    asm("cvt.rna.tf32.f32 %0, %1;" : "=r"(r) : "f"(f));
    return r;
}
__device__ __forceinline__ float tanh_ap(float x) {
    float y;
    asm("tanh.approx.f32 %0, %1;" : "=f"(y) : "f"(x));
    return y;
}
__device__ __forceinline__ void red_add(float* p, float v) {
    asm volatile("red.global.add.f32 [%0], %1;" :: "l"(p), "f"(v) : "memory");
}
// D += A(16x8 tf32) * B(8x8 tf32), fp32 accum
__device__ __forceinline__ void mma_tf32(float* d, const uint32_t* a, uint32_t b0, uint32_t b1) {
    asm volatile(
        "mma.sync.aligned.m16n8k8.row.col.f32.tf32.tf32.f32 "
        "{%0,%1,%2,%3}, {%4,%5,%6,%7}, {%8,%9}, {%0,%1,%2,%3};"
        : "+f"(d[0]), "+f"(d[1]), "+f"(d[2]), "+f"(d[3])
        : "r"(a[0]), "r"(a[1]), "r"(a[2]), "r"(a[3]), "r"(b0), "r"(b1));
}
// D += A(16x16 bf16) * B(16x8 bf16), fp32 accum
__device__ __forceinline__ void mma_bf16(float* d, const uint32_t* a, uint32_t b0, uint32_t b1) {
    asm volatile(
        "mma.sync.aligned.m16n8k16.row.col.f32.bf16.bf16.f32 "
        "{%0,%1,%2,%3}, {%4,%5,%6,%7}, {%8,%9}, {%0,%1,%2,%3};"
        : "+f"(d[0]), "+f"(d[1]), "+f"(d[2]), "+f"(d[3])
        : "r"(a[0]), "r"(a[1]), "r"(a[2]), "r"(a[3]), "r"(b0), "r"(b1));
}
// ldmatrix x4 (b16 view; loads 4 8x4-b32 matrices)
__device__ __forceinline__ void ldsm4(uint32_t* r, uint32_t saddr) {
    asm volatile("ldmatrix.sync.aligned.m8n8.x4.shared.b16 {%0,%1,%2,%3}, [%4];"
                 : "=r"(r[0]), "=r"(r[1]), "=r"(r[2]), "=r"(r[3]) : "r"(saddr));
}
__device__ __forceinline__ void cp16(uint32_t saddr, const void* g) {
    asm volatile("cp.async.cg.shared.global [%0], [%1], 16;" :: "r"(saddr), "l"(g));
}
__device__ __forceinline__ void cp_commit() {
    asm volatile("cp.async.commit_group;" ::: "memory");
}
template <int NN> __device__ __forceinline__ void cp_wait() {
    asm volatile("cp.async.wait_group %0;" :: "n"(NN) : "memory");
}

// ---------------- K0: weight prep: w -> bf16 hi/lo pairs [off][co][ci/2] -----
__global__ void wprep_kernel(const float* __restrict__ w) {
    int i = blockIdx.x * 256 + threadIdx.x;
    if (i >= 9 * 128 * 128) return;
    int off = i >> 14;
    int rem = i & 16383;
    int co = rem >> 7, j = rem & 127;
    float v0 = w[(co * 256 + 2 * j) * 9 + off];
    float v1 = w[(co * 256 + 2 * j + 1) * 9 + off];
    __nv_bfloat16 h0 = __float2bfloat16(v0), h1 = __float2bfloat16(v1);
    __nv_bfloat16 l0 = __float2bfloat16(v0 - __bfloat162float(h0));
    __nv_bfloat16 l1 = __float2bfloat16(v1 - __bfloat162float(h1));
    g_w2hi[i] = (uint32_t)__bfloat16_as_ushort(h0) |
                ((uint32_t)__bfloat16_as_ushort(h1) << 16);
    g_w2lo[i] = (uint32_t)__bfloat16_as_ushort(l0) |
                ((uint32_t)__bfloat16_as_ushort(l1) << 16);
}

// ---------------- K1: 3x3 conv via mma.sync bf16 (3xBF16 split) --------------
// 46 KB smem -> 2 CTAs/SM.  x staged as packed ci-pairs [ci/2][yy][xx].
#define XS_HI 0                       // 16 pairs x 200 = 3200
#define XS_LO 3200
#define WS_HI 6400                    // 128 co x 20 (16 words + pad) = 2560
#define WS_LO 8960
#define CONV_SMEM_WORDS 11520

__global__ __launch_bounds__(256)
void conv_tc_kernel(const float* __restrict__ x) {
    extern __shared__ uint32_t cs[];
    const int y = blockIdx.x, b = blockIdx.y;
    const int t = threadIdx.x;
    const int w = t >> 5, lane = t & 31;
    const int lq = lane >> 2, lr = lane & 3;
    const int cw = (w >> 1) * 32;
    const int pw = (w & 1) * 32;

    float acc[2][4][4];
#pragma unroll
    for (int ct = 0; ct < 2; ct++)
#pragma unroll
        for (int nt = 0; nt < 4; nt++)
#pragma unroll
            for (int i = 0; i < 4; i++) acc[ct][nt][i] = 0.f;

    for (int ci0 = 0; ci0 < CIN; ci0 += 32) {
        __syncthreads();
        // stage x tile: bf16 hi/lo packed ci-pairs
        for (int i = t; i < 32 * 198; i += 256) {
            int ci = i / 198, rem = i % 198;
            int yy = rem / 66, xx = rem % 66;
            int gy = y + yy - 1, gx = xx - 1;
            float v = 0.f;
            if (gy >= 0 && gy < HW && gx >= 0 && gx < HW)
                v = x[(((b * CIN + ci0 + ci) << 6) + gy) * 64 + gx];
            __nv_bfloat16 h = __float2bfloat16(v);
            __nv_bfloat16 l = __float2bfloat16(v - __bfloat162float(h));
            int wi = (ci >> 1) * 200 + yy * 66 + xx;
            int half = ci & 1;
            ((unsigned short*)(cs + XS_HI))[wi * 2 + half] = __bfloat16_as_ushort(h);
            ((unsigned short*)(cs + XS_LO))[wi * 2 + half] = __bfloat16_as_ushort(l);
        }

#pragma unroll 1
        for (int off = 0; off < 9; off++) {
            __syncthreads();
            {
                int base = (off << 14) + ((ci0 >> 1) & 127);
#pragma unroll
                for (int p = 0; p < 8; p++) {
                    int i = t + p * 256;
                    int co = i >> 4, j = i & 15;
                    int src = base + (co << 7) + j;
                    cs[WS_HI + co * 20 + j] = g_w2hi[src];
                    cs[WS_LO + co * 20 + j] = g_w2lo[src];
                }
            }
            __syncthreads();
            const int ky = off / 3, kx = off % 3;
            const int xb2 = ky * 66 + kx + pw;

#pragma unroll
            for (int ks = 0; ks < 2; ks++) {
                uint32_t ahi[2][4], alo[2][4];
#pragma unroll
                for (int ct = 0; ct < 2; ct++) {
                    int r = (cw + ct * 16 + lq) * 20 + ks * 8 + lr;
                    ahi[ct][0] = cs[WS_HI + r];
                    ahi[ct][1] = cs[WS_HI + r + 8 * 20];
                    ahi[ct][2] = cs[WS_HI + r + 4];
                    ahi[ct][3] = cs[WS_HI + r + 8 * 20 + 4];
                    alo[ct][0] = cs[WS_LO + r];
                    alo[ct][1] = cs[WS_LO + r + 8 * 20];
                    alo[ct][2] = cs[WS_LO + r + 4];
                    alo[ct][3] = cs[WS_LO + r + 8 * 20 + 4];
                }
#pragma unroll
                for (int nt = 0; nt < 4; nt++) {
                    int rb0 = (ks * 8 + lr) * 200 + xb2 + nt * 8 + lq;
                    int rb1 = rb0 + 4 * 200;
                    uint32_t bh0 = cs[XS_HI + rb0], bh1 = cs[XS_HI + rb1];
                    uint32_t bl0 = cs[XS_LO + rb0], bl1 = cs[XS_LO + rb1];
#pragma unroll
                    for (int ct = 0; ct < 2; ct++) {
                        mma_bf16(acc[ct][nt], ahi[ct], bh0, bh1);
                        mma_bf16(acc[ct][nt], ahi[ct], bl0, bl1);
                        mma_bf16(acc[ct][nt], alo[ct], bh0, bh1);
                    }
                }
            }
        }
    }

#pragma unroll
    for (int ct = 0; ct < 2; ct++) {
#pragma unroll
        for (int rr = 0; rr < 2; rr++) {
            int co = cw + ct * 16 + lq + rr * 8;
            float* row = &g_y[((b * C + co) << 12) + (y << 6) + pw];
#pragma unroll
            for (int nt = 0; nt < 4; nt++) {
                int m = nt * 8 + lr * 2;
                float2 vv;
                vv.x = acc[ct][nt][rr * 2];
                vv.y = acc[ct][nt][rr * 2 + 1];
                *(float2*)&row[m] = vv;
            }
        }
    }
}

// ---------------- K2: per-(channel,batch) partial stats ----------------
__global__ void bnstats1_kernel() {
    const int blk = blockIdx.x;            // 512 = c*4 + b
    const int c = blk >> 2, b = blk & 3;
    const int t = threadIdx.x;
    const float4* p = (const float4*)&g_y[(b * C + c) << 12];
    float s = 0.f, ss = 0.f;
#pragma unroll
    for (int i = 0; i < 4; i++) {
        float4 v = p[t + i * 256];
        s += v.x + v.y + v.z + v.w;
        ss += v.x * v.x + v.y * v.y + v.z * v.z + v.w * v.w;
    }
    __shared__ float r1[256], r2[256];
    r1[t] = s; r2[t] = ss;
    __syncthreads();
    for (int off = 128; off; off >>= 1) {
        if (t < off) { r1[t] += r1[t + off]; r2[t] += r2[t + off]; }
        __syncthreads();
    }
    if (t == 0) { g_bnp0[blk] = r1[0]; g_bnp1[blk] = r2[0]; }
}

// ---------------- K3: BN finalize + ReLU, d_out = 3*feat ---------------------
__global__ void bnrelu_kernel(const float* __restrict__ gamma,
                              const float* __restrict__ beta,
                              float* __restrict__ out) {
    __shared__ float sc[128], sh[128];
    const int t = threadIdx.x;
    if (t < 128) {
        float s = 0.f, ss = 0.f;
#pragma unroll
        for (int b = 0; b < 4; b++) { s += g_bnp0[t * 4 + b]; ss += g_bnp1[t * 4 + b]; }
        const float inv = 1.f / (float)(B * N);
        float mean = s * inv;
        float var  = ss * inv - mean * mean;
        float istd = rsqrtf(var + 1e-5f);
        float scv = gamma[t] * istd;
        sc[t] = scv;
        sh[t] = beta[t] - mean * scv;
    }
    __syncthreads();
    const int total = B * C * N;
    for (int i = blockIdx.x * 256 + t; i < total; i += 2048 * 256) {
        int c = (i >> 12) & (C - 1);
        float v = fmaxf(g_y[i] * sc[c] + sh[c], 0.f);
        g_y[i] = v;
        out[i] = 3.f * v;
    }
}

// ---------------- K4: qkv via mma.sync tf32 ----------------------------------
#define QK_WS 0
#define QK_FS 21120
#define QK_BIAS 30336
#define QK_WORDS 30496

__global__ __launch_bounds__(320)
void qkv_mma_kernel(const float* __restrict__ qw, const float* __restrict__ qb,
                    const float* __restrict__ kw, const float* __restrict__ kb,
                    const float* __restrict__ vw, const float* __restrict__ vb) {
    extern __shared__ uint32_t qs_[];
    const int b = blockIdx.y, n0 = blockIdx.x * 64;
    const int t = threadIdx.x;
    const int w = t >> 5, lane = t & 31;
    const int lq = lane >> 2, lr = lane & 3;

    for (int i = t; i < 160 * 128; i += 320) {
        int o = i >> 7, c = i & 127;
        float wv = (o < 16) ? qw[o * C + c]
                 : (o < 32) ? kw[(o - 16) * C + c]
                            : vw[(o - 32) * C + c];
        qs_[QK_WS + o * 132 + c] = f32_tf32(wv);
    }
    if (t < 160)
        ((float*)(qs_ + QK_BIAS))[t] = (t < 16) ? qb[t] : (t < 32 ? kb[t - 16] : vb[t - 32]);
    for (int i = t; i < 8192; i += 320) {
        int c = i >> 6, n = i & 63;
        qs_[QK_FS + c * 72 + n] = f32_tf32(g_y[((b * C + c) << 12) + n0 + n]);
    }
    __syncthreads();

    const int o0 = w * 16;
    float acc[8][4];
#pragma unroll
    for (int nt = 0; nt < 8; nt++)
#pragma unroll
        for (int i = 0; i < 4; i++) acc[nt][i] = 0.f;

#pragma unroll
    for (int ks = 0; ks < 16; ks++) {
        const int k = ks * 8;
        uint32_t a[4];
        {
            int r = (o0 + lq) * 132 + k + lr;
            a[0] = qs_[QK_WS + r];
            a[1] = qs_[QK_WS + r + 8 * 132];
            a[2] = qs_[QK_WS + r + 4];
            a[3] = qs_[QK_WS + r + 8 * 132 + 4];
        }
#pragma unroll
        for (int nt = 0; nt < 8; nt++) {
            uint32_t b0 = qs_[QK_FS + (k + lr) * 72 + nt * 8 + lq];
            uint32_t b1 = qs_[QK_FS + (k + lr + 4) * 72 + nt * 8 + lq];
            mma_tf32(acc[nt], a, b0, b1);
        }
    }

    const float* bias = (const float*)(qs_ + QK_BIAS);
#pragma unroll
    for (int rr = 0; rr < 2; rr++) {
        int o = o0 + lq + rr * 8;
        float bi = bias[o];
        uint32_t* dst = (o < 16) ? &g_q[((b * CQK + o) << 12) + n0]
                      : (o < 32) ? &g_k[((b * CQK + o - 16) << 12) + n0]
                                 : &g_v[((b * C + o - 32) << 12) + n0];
#pragma unroll
        for (int nt = 0; nt < 8; nt++) {
            int n = nt * 8 + lr * 2;
            uint2 u;
            u.x = f32_tf32(acc[nt][rr * 2] + bi);
            u.y = f32_tf32(acc[nt][rr * 2 + 1] + bi);
            *(uint2*)&dst[n] = u;
        }
    }
}

// ---------------- K5: CAM energy via mma.sync tf32, 3x split, split-k --------
#define CE_FH 0
#define CE_FL 8704
#define CE_WORDS 17408

__global__ __launch_bounds__(256)
void cam_energy_mma_kernel() {
    extern __shared__ uint32_t es[];
    const int b = blockIdx.y, s = blockIdx.x;
    const int nbase = s * (N / ESPLIT);
    const int t = threadIdx.x;
    const int w = t >> 5, lane = t & 31;
    const int lq = lane >> 2, lr = lane & 3;
    const int cw = (w & 3) * 32, dw = (w >> 2) * 64;
    const uint32_t sbase = (uint32_t)__cvta_generic_to_shared(es);

    const int aRow = lane & 15;
    const int aCol = (lane >> 4) << 2;
    const int bRow = ((lane >> 4) << 3) + (lane & 7);
    const int bCol = ((lane >> 3) & 1) << 2;

    float acc[2][8][4];
#pragma unroll
    for (int ct = 0; ct < 2; ct++)
#pragma unroll
        for (int dt = 0; dt < 8; dt++)
#pragma unroll
            for (int i = 0; i < 4; i++) acc[ct][dt][i] = 0.f;

    for (int it = 0; it < 4; it++) {
        const int n0 = nbase + it * 64;
        __syncthreads();
        for (int i = t; i < 8192; i += 256) {
            int c = i >> 6, n = i & 63;
            float v = g_y[((b * C + c) << 12) + n0 + n];
            uint32_t hi = f32_tf32(v);
            es[CE_FH + c * 68 + n] = hi;
            es[CE_FL + c * 68 + n] = f32_tf32(v - __uint_as_float(hi));
        }
        __syncthreads();

#pragma unroll
        for (int ks = 0; ks < 8; ks++) {
            const int k = ks * 8;
            uint32_t ah[2][4], al[2][4];
#pragma unroll
            for (int ct = 0; ct < 2; ct++) {
                uint32_t ao = (uint32_t)((cw + ct * 16 + aRow) * 68 + aCol + k);
                ldsm4(ah[ct], sbase + (CE_FH + ao) * 4);
                ldsm4(al[ct], sbase + (CE_FL + ao) * 4);
            }
#pragma unroll
            for (int p = 0; p < 4; p++) {
                uint32_t bo = (uint32_t)((dw + 16 * p + bRow) * 68 + bCol + k);
                uint32_t bh[4], bl[4];
                ldsm4(bh, sbase + (CE_FH + bo) * 4);
                ldsm4(bl, sbase + (CE_FL + bo) * 4);
#pragma unroll
                for (int ct = 0; ct < 2; ct++) {
                    mma_tf32(acc[ct][2 * p],     ah[ct], bh[0], bh[1]);
                    mma_tf32(acc[ct][2 * p],     ah[ct], bl[0], bl[1]);
                    mma_tf32(acc[ct][2 * p],     al[ct], bh[0], bh[1]);
                    mma_tf32(acc[ct][2 * p + 1], ah[ct], bh[2], bh[3]);
                    mma_tf32(acc[ct][2 * p + 1], ah[ct], bl[2], bl[3]);
                    mma_tf32(acc[ct][2 * p + 1], al[ct], bh[2], bh[3]);
                }
            }
        }
    }

    float* ep = &g_ep[(s * B + b) << 14];
#pragma unroll
    for (int ct = 0; ct < 2; ct++) {
#pragma unroll
        for (int rr = 0; rr < 2; rr++) {
            int c = cw + ct * 16 + lq + rr * 8;
#pragma unroll
            for (int dt = 0; dt < 8; dt++) {
                int d = dw + dt * 8 + lr * 2;
                float2 vv;
                vv.x = acc[ct][dt][rr * 2];
                vv.y = acc[ct][dt][rr * 2 + 1];
                *(float2*)&ep[(c << 7) + d] = vv;
            }
        }
    }
}

// ---------------- K6: CAM reduce: sum partials, attn = tanh(rowmax - e) ------
__global__ void cam_reduce_kernel() {
    const int b = blockIdx.y, c = blockIdx.x, t = threadIdx.x; // 128 threads
    float e = 0.f;
#pragma unroll
    for (int s = 0; s < ESPLIT; s++)
        e += g_ep[((s * B + b) << 14) + (c << 7) + t];
    __shared__ float red[128];
    red[t] = e;
    __syncthreads();
    for (int off = 64; off; off >>= 1) {
        if (t < off) red[t] = fmaxf(red[t], red[t + off]);
        __syncthreads();
    }
    g_e[((b * C + c) << 7) + t] = tanhf(red[0] - e);
}

// ---------------- K7: CAM out via mma.sync tf32 (atomic out += ) -------------
#define CO_AS 0
#define CO_FS 16896
#define CO_WORDS 34304

__global__ __launch_bounds__(256)
void cam_out_mma_kernel(const float* __restrict__ gca, float* __restrict__ out) {
    extern __shared__ uint32_t os_[];
    const int b = blockIdx.y, nb = blockIdx.x * 128;
    const int t = threadIdx.x;
    const int w = t >> 5, lane = t & 31;
    const int lq = lane >> 2, lr = lane & 3;
    const int cw = (w & 3) * 32, nw = (w >> 2) * 64;

    for (int i = t; i < 16384; i += 256) {
        int c = i >> 7, d = i & 127;
        os_[CO_AS + c * 132 + d] = f32_tf32(g_e[((b * C + c) << 7) + d]);
    }
    for (int i = t; i < 16384; i += 256) {
        int d = i >> 7, n = i & 127;
        os_[CO_FS + d * 136 + n] = f32_tf32(g_y[((b * C + d) << 12) + nb + n]);
    }
    __syncthreads();

    float acc[2][8][4];
#pragma unroll
    for (int ct = 0; ct < 2; ct++)
#pragma unroll
        for (int nt = 0; nt < 8; nt++)
#pragma unroll
            for (int i = 0; i < 4; i++) acc[ct][nt][i] = 0.f;

#pragma unroll
    for (int ks = 0; ks < 16; ks++) {
        const int k = ks * 8;
        uint32_t a[2][4];
#pragma unroll
        for (int ct = 0; ct < 2; ct++) {
            int r = (cw + ct * 16 + lq) * 132 + k + lr;
            a[ct][0] = os_[CO_AS + r];
            a[ct][1] = os_[CO_AS + r + 8 * 132];
            a[ct][2] = os_[CO_AS + r + 4];
            a[ct][3] = os_[CO_AS + r + 8 * 132 + 4];
        }
#pragma unroll
        for (int nt = 0; nt < 8; nt++) {
            uint32_t b0 = os_[CO_FS + (k + lr) * 136 + nw + nt * 8 + lq];
            uint32_t b1 = os_[CO_FS + (k + lr + 4) * 136 + nw + nt * 8 + lq];
#pragma unroll
            for (int ct = 0; ct < 2; ct++)
                mma_tf32(acc[ct][nt], a[ct], b0, b1);
        }
    }

    const float g = gca[0];
#pragma unroll
    for (int ct = 0; ct < 2; ct++) {
#pragma unroll
        for (int rr = 0; rr < 2; rr++) {
            int c = cw + ct * 16 + lq + rr * 8;
            float* row = &out[((b * C + c) << 12) + nb + nw];
#pragma unroll
            for (int nt = 0; nt < 8; nt++) {
                int n = nt * 8 + lr * 2;
                red_add(&row[n],     g * acc[ct][nt][rr * 2]);
                red_add(&row[n + 1], g * acc[ct][nt][rr * 2 + 1]);
            }
        }
    }
}

// ---------------- K8: PAM: m-tile 128, n-chunk 64, 3-stage cp.async ----------
#define P_QS 0
#define P_KS 2560
#define P_VS 5824
#define P_SN 31936
#define P_WORDS 40640

__global__ __launch_bounds__(256, 1)
void pam_mma_kernel(const float* __restrict__ gpa, float* __restrict__ out) {
    extern __shared__ uint32_t ps[];
    const int b = blockIdx.y, m0 = blockIdx.x * 128;
    const int t = threadIdx.x;
    const int w = t >> 5, lane = t & 31;
    const int lq = lane >> 2, lr = lane & 3;
    const uint32_t sbase = (uint32_t)__cvta_generic_to_shared(ps);

    for (int i = t; i < 2048; i += 256) {
        int qc = i >> 7, m = i & 127;
        ps[P_QS + m * 20 + qc] = g_q[((b * CQK + qc) << 12) + m0 + m];
    }

    const int krow = t >> 4, kc4 = (t & 15) * 4;
    const uint32_t kdst = sbase + (P_KS + krow * 68 + kc4) * 4;
    const uint32_t* kgsrc = &g_k[((b * CQK + krow) << 12) + kc4];
    const uint32_t vdst = sbase + (P_VS + krow * 68 + kc4) * 4;
    const uint32_t* vgsrc = &g_v[((b * C + krow) << 12) + kc4];

    cp16(kdst, kgsrc);
#pragma unroll
    for (int p = 0; p < 8; p++)
        cp16(vdst + p * 16 * 68 * 4, vgsrc + (p << 16));
    cp_commit();
    cp16(kdst + 1088 * 4, kgsrc + 64);
#pragma unroll
    for (int p = 0; p < 8; p++)
        cp16(vdst + (8704 + p * 16 * 68) * 4, vgsrc + (p << 16) + 64);
    cp_commit();

    __syncthreads();

    uint32_t aq[2][4];
#pragma unroll
    for (int ks = 0; ks < 2; ks++) {
        int r = w * 16 + lq, c = ks * 8 + lr;
        aq[ks][0] = ps[P_QS + r * 20 + c];
        aq[ks][1] = ps[P_QS + (r + 8) * 20 + c];
        aq[ks][2] = ps[P_QS + r * 20 + c + 4];
        aq[ks][3] = ps[P_QS + (r + 8) * 20 + c + 4];
    }

    const int cw = (w & 3) * 32, mw = (w >> 2) * 64;

    const int aRow = lane & 15;
    const int aCol = (lane >> 4) << 2;
    const int bRow = ((lane >> 4) << 3) + (lane & 7);
    const int bCol = ((lane >> 3) & 1) << 2;
    uint32_t aOff[2], bOff[4];
#pragma unroll
    for (int ct = 0; ct < 2; ct++)
        aOff[ct] = (uint32_t)((cw + ct * 16 + aRow) * 68 + aCol);
#pragma unroll
    for (int p = 0; p < 4; p++)
        bOff[p] = (uint32_t)(P_SN + (mw + 16 * p + bRow) * 68 + bCol);

    float acc[2][8][4];
#pragma unroll
    for (int ct = 0; ct < 2; ct++)
#pragma unroll
        for (int mt = 0; mt < 8; mt++)
#pragma unroll
            for (int i = 0; i < 4; i++) acc[ct][mt][i] = 0.f;

    int sc = 0, sp = 2;
#pragma unroll 1
    for (int ch = 0; ch < 64; ch++) {
        cp_wait<1>();
        __syncthreads();

        if (ch + 2 < 64) {
            const int n2 = (ch + 2) * 64;
            cp16(kdst + sp * 1088 * 4, kgsrc + n2);
#pragma unroll
            for (int p = 0; p < 8; p++)
                cp16(vdst + (sp * 8704 + p * 16 * 68) * 4, vgsrc + (p << 16) + n2);
        }
        cp_commit();

        const uint32_t* ksb = ps + P_KS + sc * 1088;
        const uint32_t vWordBase = (uint32_t)(P_VS + sc * 8704);

        float e[8][4];
#pragma unroll
        for (int ni = 0; ni < 8; ni++) {
#pragma unroll
            for (int i = 0; i < 4; i++) e[ni][i] = 0.f;
#pragma unroll
            for (int ks = 0; ks < 2; ks++) {
                uint32_t b0 = ksb[(ks * 8 + lr) * 68 + ni * 8 + lq];
                uint32_t b1 = ksb[(ks * 8 + lr + 4) * 68 + ni * 8 + lq];
                mma_tf32(e[ni], aq[ks], b0, b1);
            }
        }
        {
            int m = w * 16 + lq;
#pragma unroll
            for (int ni = 0; ni < 8; ni++) {
                int n = ni * 8 + lr * 2;
                uint2 u0, u1;
                u0.x = f32_tf32(tanh_ap(e[ni][0]));
                u0.y = f32_tf32(tanh_ap(e[ni][1]));
                u1.x = f32_tf32(tanh_ap(e[ni][2]));
                u1.y = f32_tf32(tanh_ap(e[ni][3]));
                *(uint2*)&ps[P_SN + m * 68 + n]       = u0;
                *(uint2*)&ps[P_SN + (m + 8) * 68 + n] = u1;
            }
        }
        __syncthreads();

#pragma unroll
        for (int ks = 0; ks < 8; ks++) {
            const int k = ks * 8;
            uint32_t a[2][4], bb8[4][4];
#pragma unroll
            for (int ct = 0; ct < 2; ct++)
                ldsm4(a[ct], sbase + (vWordBase + aOff[ct] + k) * 4);
#pragma unroll
            for (int p = 0; p < 4; p++)
                ldsm4(bb8[p], sbase + (bOff[p] + k) * 4);
#pragma unroll
            for (int ct = 0; ct < 2; ct++)
#pragma unroll
                for (int mt = 0; mt < 8; mt++)
                    mma_tf32(acc[ct][mt], a[ct], bb8[mt >> 1][(mt & 1) * 2],
                             bb8[mt >> 1][(mt & 1) * 2 + 1]);
        }

        sc = (sc == 2) ? 0 : sc + 1;
        sp = (sp == 2) ? 0 : sp + 1;
    }

    const float g = gpa[0];
#pragma unroll
    for (int ct = 0; ct < 2; ct++) {
#pragma unroll
        for (int rr = 0; rr < 2; rr++) {
            int c = cw + ct * 16 + lq + rr * 8;
            float* row = &out[((b * C + c) << 12) + m0 + mw];
#pragma unroll
            for (int mt = 0; mt < 8; mt++) {
                int m = mt * 8 + lr * 2;
                red_add(&row[m],     g * acc[ct][mt][rr * 2]);
                red_add(&row[m + 1], g * acc[ct][mt][rr * 2 + 1]);
            }
        }
    }
}

// ---------------- launch (forked streams: CAM chain || qkv+PAM) --------------
extern "C" void kernel_launch(void* const* d_in, const int* in_sizes, int n_in,
                              void* d_out, int out_size) {
    const float* x       = (const float*)d_in[0];
    const float* conv_w  = (const float*)d_in[1];
    const float* bn_g    = (const float*)d_in[2];
    const float* bn_b    = (const float*)d_in[3];
    const float* q_w     = (const float*)d_in[4];
    const float* q_b     = (const float*)d_in[5];
    const float* k_w     = (const float*)d_in[6];
    const float* k_b     = (const float*)d_in[7];
    const float* v_w     = (const float*)d_in[8];
    const float* v_b     = (const float*)d_in[9];
    const float* gca     = (const float*)d_in[10];
    const float* gpa     = (const float*)d_in[11];
    float* out = (float*)d_out;

    static cudaStream_t sA = nullptr, sB = nullptr;
    static cudaEvent_t ev0 = nullptr, evA = nullptr, evB = nullptr;
    if (!sA) {
        cudaStreamCreateWithFlags(&sA, cudaStreamNonBlocking);
        cudaStreamCreateWithFlags(&sB, cudaStreamNonBlocking);
        cudaEventCreateWithFlags(&ev0, cudaEventDisableTiming);
        cudaEventCreateWithFlags(&evA, cudaEventDisableTiming);
        cudaEventCreateWithFlags(&evB, cudaEventDisableTiming);

        cudaFuncSetAttribute(conv_tc_kernel, cudaFuncAttributeMaxDynamicSharedMemorySize,
                             CONV_SMEM_WORDS * 4);
        cudaFuncSetAttribute(pam_mma_kernel, cudaFuncAttributeMaxDynamicSharedMemorySize,
                             P_WORDS * 4);
        cudaFuncSetAttribute(qkv_mma_kernel, cudaFuncAttributeMaxDynamicSharedMemorySize,
                             QK_WORDS * 4);
        cudaFuncSetAttribute(cam_energy_mma_kernel, cudaFuncAttributeMaxDynamicSharedMemorySize,
                             CE_WORDS * 4);
        cudaFuncSetAttribute(cam_out_mma_kernel, cudaFuncAttributeMaxDynamicSharedMemorySize,
                             CO_WORDS * 4);
    }

    // serial prologue on the launch stream
    wprep_kernel<<<576, 256>>>(conv_w);
    conv_tc_kernel<<<dim3(64, B), 256, CONV_SMEM_WORDS * 4>>>(x);
    bnstats1_kernel<<<512, 256>>>();
    bnrelu_kernel<<<2048, 256>>>(bn_g, bn_b, out);

    // fork
    cudaEventRecord(ev0, 0);
    cudaStreamWaitEvent(sA, ev0, 0);
    cudaStreamWaitEvent(sB, ev0, 0);

    // stream A: CAM chain (atomic adds into out)
    cam_energy_mma_kernel<<<dim3(ESPLIT, B), 256, CE_WORDS * 4, sA>>>();
    cam_reduce_kernel<<<dim3(C, B), 128, 0, sA>>>();
    cam_out_mma_kernel<<<dim3(32, B), 256, CO_WORDS * 4, sA>>>(gca, out);

    // stream B: qkv -> PAM (atomic adds into out)
    qkv_mma_kernel<<<dim3(64, B), 320, QK_WORDS * 4, sB>>>(q_w, q_b, k_w, k_b, v_w, v_b);
    pam_mma_kernel<<<dim3(32, B), 256, P_WORDS * 4, sB>>>(gpa, out);

    // join
    cudaEventRecord(evA, sA);
    cudaEventRecord(evB, sB);
    cudaStreamWaitEvent(0, evA, 0);
    cudaStreamWaitEvent(0, evB, 0);
}

// round 14
// speedup vs baseline: 1.3082x; 1.0046x over previous
#include <cuda_runtime.h>
#include <cuda_bf16.h>
#include <math.h>
#include <stdint.h>

// Problem constants
#define B   4
#define CIN 256
#define C   128
#define HW  64
#define N   4096          // HW*HW
#define CQK 16
#define ESPLIT 16         // CAM energy split-k slices

// ---------------- scratch (device globals; no allocation) ----------------
__device__ float g_y[B * C * N];        // conv out, then feat (in-place) : 8 MB
__device__ float g_bnp0[512];
__device__ float g_bnp1[512];
__device__ uint32_t g_q[B * CQK * N];   // tf32 bits
__device__ uint32_t g_k[B * CQK * N];   // tf32 bits
__device__ uint32_t g_v[B * C * N];     // tf32 bits : 8 MB
__device__ float g_e[B * C * C];        // CAM attn
__device__ float g_ep[ESPLIT * B * C * C];  // CAM energy partials : 4 MB
__device__ uint32_t g_w2hi[9 * 128 * 128];  // conv w, bf16x2 hi pairs [off][co][ci/2]
__device__ uint32_t g_w2lo[9 * 128 * 128];  // bf16x2 residual pairs

// ================= base-ISA tensor helpers (NO tcgen05 — plain sm_103) ======
__device__ __forceinline__ uint32_t f32_tf32(float f) {
    uint32_t r;
    asm("cvt.rna.tf32.f32 %0, %1;" : "=r"(r) : "f"(f));
    return r;
}
__device__ __forceinline__ float tanh_ap(float x) {
    float y;
    asm("tanh.approx.f32 %0, %1;" : "=f"(y) : "f"(x));
    return y;
}
__device__ __forceinline__ void red_add(float* p, float v) {
    asm volatile("red.global.add.f32 [%0], %1;" :: "l"(p), "f"(v) : "memory");
}
// D += A(16x8 tf32) * B(8x8 tf32), fp32 accum
__device__ __forceinline__ void mma_tf32(float* d, const uint32_t* a, uint32_t b0, uint32_t b1) {
    asm volatile(
        "mma.sync.aligned.m16n8k8.row.col.f32.tf32.tf32.f32 "
        "{%0,%1,%2,%3}, {%4,%5,%6,%7}, {%8,%9}, {%0,%1,%2,%3};"
        : "+f"(d[0]), "+f"(d[1]), "+f"(d[2]), "+f"(d[3])
        : "r"(a[0]), "r"(a[1]), "r"(a[2]), "r"(a[3]), "r"(b0), "r"(b1));
}
// D += A(16x16 bf16) * B(16x8 bf16), fp32 accum
__device__ __forceinline__ void mma_bf16(float* d, const uint32_t* a, uint32_t b0, uint32_t b1) {
    asm volatile(
        "mma.sync.aligned.m16n8k16.row.col.f32.bf16.bf16.f32 "
        "{%0,%1,%2,%3}, {%4,%5,%6,%7}, {%8,%9}, {%0,%1,%2,%3};"
        : "+f"(d[0]), "+f"(d[1]), "+f"(d[2]), "+f"(d[3])
        : "r"(a[0]), "r"(a[1]), "r"(a[2]), "r"(a[3]), "r"(b0), "r"(b1));
}
// ldmatrix x4 (b16 view; loads 4 8x4-b32 matrices)
__device__ __forceinline__ void ldsm4(uint32_t* r, uint32_t saddr) {
    asm volatile("ldmatrix.sync.aligned.m8n8.x4.shared.b16 {%0,%1,%2,%3}, [%4];"
                 : "=r"(r[0]), "=r"(r[1]), "=r"(r[2]), "=r"(r[3]) : "r"(saddr));
}
__device__ __forceinline__ void cp16(uint32_t saddr, const void* g) {
    asm volatile("cp.async.cg.shared.global [%0], [%1], 16;" :: "r"(saddr), "l"(g));
}
__device__ __forceinline__ void cp_commit() {
    asm volatile("cp.async.commit_group;" ::: "memory");
}
template <int NN> __device__ __forceinline__ void cp_wait() {
    asm volatile("cp.async.wait_group %0;" :: "n"(NN) : "memory");
}

// ---------------- K0: weight prep: w -> bf16 hi/lo pairs [off][co][ci/2] -----
__global__ void wprep_kernel(const float* __restrict__ w) {
    int i = blockIdx.x * 256 + threadIdx.x;
    if (i >= 9 * 128 * 128) return;
    int off = i >> 14;
    int rem = i & 16383;
    int co = rem >> 7, j = rem & 127;
    float v0 = w[(co * 256 + 2 * j) * 9 + off];
    float v1 = w[(co * 256 + 2 * j + 1) * 9 + off];
    __nv_bfloat16 h0 = __float2bfloat16(v0), h1 = __float2bfloat16(v1);
    __nv_bfloat16 l0 = __float2bfloat16(v0 - __bfloat162float(h0));
    __nv_bfloat16 l1 = __float2bfloat16(v1 - __bfloat162float(h1));
    g_w2hi[i] = (uint32_t)__bfloat16_as_ushort(h0) |
                ((uint32_t)__bfloat16_as_ushort(h1) << 16);
    g_w2lo[i] = (uint32_t)__bfloat16_as_ushort(l0) |
                ((uint32_t)__bfloat16_as_ushort(l1) << 16);
}

// ---------------- K1: 3x3 conv via mma.sync bf16 (3xBF16 split) --------------
// ci-chunk 16 (= one k16 MMA step); ALL 9 offsets' weights staged per chunk
// via cp.async -> 2 barriers per chunk, 32 total.  86.5 KB smem -> 2 CTAs/SM.
#define XS_HI 0                       // 8 pairs x 200 = 1600
#define XS_LO 1600
#define WS_HI 3200                    // 9 off x 128 co x 8 words = 9216
#define WS_LO 12416
#define CONV_SMEM_WORDS 21632         // 86528 B

__global__ __launch_bounds__(256)
void conv_tc_kernel(const float* __restrict__ x) {
    extern __shared__ uint32_t cs[];
    const int y = blockIdx.x, b = blockIdx.y;
    const int t = threadIdx.x;
    const int w = t >> 5, lane = t & 31;
    const int lq = lane >> 2, lr = lane & 3;
    const int cw = (w >> 1) * 32;
    const int pw = (w & 1) * 32;
    const uint32_t sbase = (uint32_t)__cvta_generic_to_shared(cs);

    float acc[2][4][4];
#pragma unroll
    for (int ct = 0; ct < 2; ct++)
#pragma unroll
        for (int nt = 0; nt < 4; nt++)
#pragma unroll
            for (int i = 0; i < 4; i++) acc[ct][nt][i] = 0.f;

#pragma unroll 1
    for (int ci0 = 0; ci0 < CIN; ci0 += 16) {
        __syncthreads();   // everyone done with previous chunk's tiles
        // weights for ALL 9 offsets, this ci-chunk (cp.async, 2x 16B per (off,co))
        {
            const int pb = ci0 >> 1;   // pair base
#pragma unroll
            for (int p = 0; p < 9; p++) {
                int i = t + p * 256;   // 2304 total
                int off = i >> 8, rem = i & 255;
                int co = rem >> 1, half = (rem & 1) << 2;
                uint32_t d = (uint32_t)(off * 1024 + co * 8 + half);
                int src = (off << 14) + (co << 7) + pb + half;
                cp16(sbase + (WS_HI + d) * 4, g_w2hi + src);
                cp16(sbase + (WS_LO + d) * 4, g_w2lo + src);
            }
        }
        // x tile: 16 ci x 3 rows x 66 px, bf16 hi/lo packed ci-pairs
        for (int i = t; i < 16 * 198; i += 256) {
            int ci = i / 198, rem = i % 198;
            int yy = rem / 66, xx = rem % 66;
            int gy = y + yy - 1, gx = xx - 1;
            float v = 0.f;
            if (gy >= 0 && gy < HW && gx >= 0 && gx < HW)
                v = x[(((b * CIN + ci0 + ci) << 6) + gy) * 64 + gx];
            __nv_bfloat16 h = __float2bfloat16(v);
            __nv_bfloat16 l = __float2bfloat16(v - __bfloat162float(h));
            int wi = (ci >> 1) * 200 + yy * 66 + xx;
            int half = ci & 1;
            ((unsigned short*)(cs + XS_HI))[wi * 2 + half] = __bfloat16_as_ushort(h);
            ((unsigned short*)(cs + XS_LO))[wi * 2 + half] = __bfloat16_as_ushort(l);
        }
        cp_commit();
        cp_wait<0>();
        __syncthreads();

#pragma unroll 1
        for (int off = 0; off < 9; off++) {
            const int ky = off / 3, kx = off % 3;
            const int xb2 = ky * 66 + kx + pw;
            const int wb = off * 1024;

            uint32_t ahi[2][4], alo[2][4];
#pragma unroll
            for (int ct = 0; ct < 2; ct++) {
                int r = wb + (cw + ct * 16 + lq) * 8 + lr;
                ahi[ct][0] = cs[WS_HI + r];
                ahi[ct][1] = cs[WS_HI + r + 64];
                ahi[ct][2] = cs[WS_HI + r + 4];
                ahi[ct][3] = cs[WS_HI + r + 68];
                alo[ct][0] = cs[WS_LO + r];
                alo[ct][1] = cs[WS_LO + r + 64];
                alo[ct][2] = cs[WS_LO + r + 4];
                alo[ct][3] = cs[WS_LO + r + 68];
            }
#pragma unroll
            for (int nt = 0; nt < 4; nt++) {
                int rb0 = lr * 200 + xb2 + nt * 8 + lq;
                int rb1 = rb0 + 4 * 200;
                uint32_t bh0 = cs[XS_HI + rb0], bh1 = cs[XS_HI + rb1];
                uint32_t bl0 = cs[XS_LO + rb0], bl1 = cs[XS_LO + rb1];
#pragma unroll
                for (int ct = 0; ct < 2; ct++) {
                    mma_bf16(acc[ct][nt], ahi[ct], bh0, bh1);
                    mma_bf16(acc[ct][nt], ahi[ct], bl0, bl1);
                    mma_bf16(acc[ct][nt], alo[ct], bh0, bh1);
                }
            }
        }
    }

#pragma unroll
    for (int ct = 0; ct < 2; ct++) {
#pragma unroll
        for (int rr = 0; rr < 2; rr++) {
            int co = cw + ct * 16 + lq + rr * 8;
            float* row = &g_y[((b * C + co) << 12) + (y << 6) + pw];
#pragma unroll
            for (int nt = 0; nt < 4; nt++) {
                int m = nt * 8 + lr * 2;
                float2 vv;
                vv.x = acc[ct][nt][rr * 2];
                vv.y = acc[ct][nt][rr * 2 + 1];
                *(float2*)&row[m] = vv;
            }
        }
    }
}

// ---------------- K2: per-(channel,batch) partial stats ----------------
__global__ void bnstats1_kernel() {
    const int blk = blockIdx.x;            // 512 = c*4 + b
    const int c = blk >> 2, b = blk & 3;
    const int t = threadIdx.x;
    const float4* p = (const float4*)&g_y[(b * C + c) << 12];
    float s = 0.f, ss = 0.f;
#pragma unroll
    for (int i = 0; i < 4; i++) {
        float4 v = p[t + i * 256];
        s += v.x + v.y + v.z + v.w;
        ss += v.x * v.x + v.y * v.y + v.z * v.z + v.w * v.w;
    }
    __shared__ float r1[256], r2[256];
    r1[t] = s; r2[t] = ss;
    __syncthreads();
    for (int off = 128; off; off >>= 1) {
        if (t < off) { r1[t] += r1[t + off]; r2[t] += r2[t + off]; }
        __syncthreads();
    }
    if (t == 0) { g_bnp0[blk] = r1[0]; g_bnp1[blk] = r2[0]; }
}

// ---------------- K3: BN finalize + ReLU, d_out = 3*feat ---------------------
__global__ void bnrelu_kernel(const float* __restrict__ gamma,
                              const float* __restrict__ beta,
                              float* __restrict__ out) {
    __shared__ float sc[128], sh[128];
    const int t = threadIdx.x;
    if (t < 128) {
        float s = 0.f, ss = 0.f;
#pragma unroll
        for (int b = 0; b < 4; b++) { s += g_bnp0[t * 4 + b]; ss += g_bnp1[t * 4 + b]; }
        const float inv = 1.f / (float)(B * N);
        float mean = s * inv;
        float var  = ss * inv - mean * mean;
        float istd = rsqrtf(var + 1e-5f);
        float scv = gamma[t] * istd;
        sc[t] = scv;
        sh[t] = beta[t] - mean * scv;
    }
    __syncthreads();
    const int total = B * C * N;
    for (int i = blockIdx.x * 256 + t; i < total; i += 2048 * 256) {
        int c = (i >> 12) & (C - 1);
        float v = fmaxf(g_y[i] * sc[c] + sh[c], 0.f);
        g_y[i] = v;
        out[i] = 3.f * v;
    }
}

// ---------------- K4: qkv via mma.sync tf32 ----------------------------------
#define QK_WS 0
#define QK_FS 21120
#define QK_BIAS 30336
#define QK_WORDS 30496

__global__ __launch_bounds__(320)
void qkv_mma_kernel(const float* __restrict__ qw, const float* __restrict__ qb,
                    const float* __restrict__ kw, const float* __restrict__ kb,
                    const float* __restrict__ vw, const float* __restrict__ vb) {
    extern __shared__ uint32_t qs_[];
    const int b = blockIdx.y, n0 = blockIdx.x * 64;
    const int t = threadIdx.x;
    const int w = t >> 5, lane = t & 31;
    const int lq = lane >> 2, lr = lane & 3;

    for (int i = t; i < 160 * 128; i += 320) {
        int o = i >> 7, c = i & 127;
        float wv = (o < 16) ? qw[o * C + c]
                 : (o < 32) ? kw[(o - 16) * C + c]
                            : vw[(o - 32) * C + c];
        qs_[QK_WS + o * 132 + c] = f32_tf32(wv);
    }
    if (t < 160)
        ((float*)(qs_ + QK_BIAS))[t] = (t < 16) ? qb[t] : (t < 32 ? kb[t - 16] : vb[t - 32]);
    for (int i = t; i < 8192; i += 320) {
        int c = i >> 6, n = i & 63;
        qs_[QK_FS + c * 72 + n] = f32_tf32(g_y[((b * C + c) << 12) + n0 + n]);
    }
    __syncthreads();

    const int o0 = w * 16;
    float acc[8][4];
#pragma unroll
    for (int nt = 0; nt < 8; nt++)
#pragma unroll
        for (int i = 0; i < 4; i++) acc[nt][i] = 0.f;

#pragma unroll
    for (int ks = 0; ks < 16; ks++) {
        const int k = ks * 8;
        uint32_t a[4];
        {
            int r = (o0 + lq) * 132 + k + lr;
            a[0] = qs_[QK_WS + r];
            a[1] = qs_[QK_WS + r + 8 * 132];
            a[2] = qs_[QK_WS + r + 4];
            a[3] = qs_[QK_WS + r + 8 * 132 + 4];
        }
#pragma unroll
        for (int nt = 0; nt < 8; nt++) {
            uint32_t b0 = qs_[QK_FS + (k + lr) * 72 + nt * 8 + lq];
            uint32_t b1 = qs_[QK_FS + (k + lr + 4) * 72 + nt * 8 + lq];
            mma_tf32(acc[nt], a, b0, b1);
        }
    }

    const float* bias = (const float*)(qs_ + QK_BIAS);
#pragma unroll
    for (int rr = 0; rr < 2; rr++) {
        int o = o0 + lq + rr * 8;
        float bi = bias[o];
        uint32_t* dst = (o < 16) ? &g_q[((b * CQK + o) << 12) + n0]
                      : (o < 32) ? &g_k[((b * CQK + o - 16) << 12) + n0]
                                 : &g_v[((b * C + o - 32) << 12) + n0];
#pragma unroll
        for (int nt = 0; nt < 8; nt++) {
            int n = nt * 8 + lr * 2;
            uint2 u;
            u.x = f32_tf32(acc[nt][rr * 2] + bi);
            u.y = f32_tf32(acc[nt][rr * 2 + 1] + bi);
            *(uint2*)&dst[n] = u;
        }
    }
}

// ---------------- K5: CAM energy via mma.sync tf32, 3x split, split-k --------
#define CE_FH 0
#define CE_FL 8704
#define CE_WORDS 17408

__global__ __launch_bounds__(256)
void cam_energy_mma_kernel() {
    extern __shared__ uint32_t es[];
    const int b = blockIdx.y, s = blockIdx.x;
    const int nbase = s * (N / ESPLIT);
    const int t = threadIdx.x;
    const int w = t >> 5, lane = t & 31;
    const int lq = lane >> 2, lr = lane & 3;
    const int cw = (w & 3) * 32, dw = (w >> 2) * 64;
    const uint32_t sbase = (uint32_t)__cvta_generic_to_shared(es);

    const int aRow = lane & 15;
    const int aCol = (lane >> 4) << 2;
    const int bRow = ((lane >> 4) << 3) + (lane & 7);
    const int bCol = ((lane >> 3) & 1) << 2;

    float acc[2][8][4];
#pragma unroll
    for (int ct = 0; ct < 2; ct++)
#pragma unroll
        for (int dt = 0; dt < 8; dt++)
#pragma unroll
            for (int i = 0; i < 4; i++) acc[ct][dt][i] = 0.f;

    for (int it = 0; it < 4; it++) {
        const int n0 = nbase + it * 64;
        __syncthreads();
        for (int i = t; i < 8192; i += 256) {
            int c = i >> 6, n = i & 63;
            float v = g_y[((b * C + c) << 12) + n0 + n];
            uint32_t hi = f32_tf32(v);
            es[CE_FH + c * 68 + n] = hi;
            es[CE_FL + c * 68 + n] = f32_tf32(v - __uint_as_float(hi));
        }
        __syncthreads();

#pragma unroll
        for (int ks = 0; ks < 8; ks++) {
            const int k = ks * 8;
            uint32_t ah[2][4], al[2][4];
#pragma unroll
            for (int ct = 0; ct < 2; ct++) {
                uint32_t ao = (uint32_t)((cw + ct * 16 + aRow) * 68 + aCol + k);
                ldsm4(ah[ct], sbase + (CE_FH + ao) * 4);
                ldsm4(al[ct], sbase + (CE_FL + ao) * 4);
            }
#pragma unroll
            for (int p = 0; p < 4; p++) {
                uint32_t bo = (uint32_t)((dw + 16 * p + bRow) * 68 + bCol + k);
                uint32_t bh[4], bl[4];
                ldsm4(bh, sbase + (CE_FH + bo) * 4);
                ldsm4(bl, sbase + (CE_FL + bo) * 4);
#pragma unroll
                for (int ct = 0; ct < 2; ct++) {
                    mma_tf32(acc[ct][2 * p],     ah[ct], bh[0], bh[1]);
                    mma_tf32(acc[ct][2 * p],     ah[ct], bl[0], bl[1]);
                    mma_tf32(acc[ct][2 * p],     al[ct], bh[0], bh[1]);
                    mma_tf32(acc[ct][2 * p + 1], ah[ct], bh[2], bh[3]);
                    mma_tf32(acc[ct][2 * p + 1], ah[ct], bl[2], bl[3]);
                    mma_tf32(acc[ct][2 * p + 1], al[ct], bh[2], bh[3]);
                }
            }
        }
    }

    float* ep = &g_ep[(s * B + b) << 14];
#pragma unroll
    for (int ct = 0; ct < 2; ct++) {
#pragma unroll
        for (int rr = 0; rr < 2; rr++) {
            int c = cw + ct * 16 + lq + rr * 8;
#pragma unroll
            for (int dt = 0; dt < 8; dt++) {
                int d = dw + dt * 8 + lr * 2;
                float2 vv;
                vv.x = acc[ct][dt][rr * 2];
                vv.y = acc[ct][dt][rr * 2 + 1];
                *(float2*)&ep[(c << 7) + d] = vv;
            }
        }
    }
}

// ---------------- K6: CAM reduce: sum partials, attn = tanh(rowmax - e) ------
__global__ void cam_reduce_kernel() {
    const int b = blockIdx.y, c = blockIdx.x, t = threadIdx.x; // 128 threads
    float e = 0.f;
#pragma unroll
    for (int s = 0; s < ESPLIT; s++)
        e += g_ep[((s * B + b) << 14) + (c << 7) + t];
    __shared__ float red[128];
    red[t] = e;
    __syncthreads();
    for (int off = 64; off; off >>= 1) {
        if (t < off) red[t] = fmaxf(red[t], red[t + off]);
        __syncthreads();
    }
    g_e[((b * C + c) << 7) + t] = tanhf(red[0] - e);
}

// ---------------- K7: CAM out via mma.sync tf32 (atomic out += ) -------------
#define CO_AS 0
#define CO_FS 16896
#define CO_WORDS 34304

__global__ __launch_bounds__(256)
void cam_out_mma_kernel(const float* __restrict__ gca, float* __restrict__ out) {
    extern __shared__ uint32_t os_[];
    const int b = blockIdx.y, nb = blockIdx.x * 128;
    const int t = threadIdx.x;
    const int w = t >> 5, lane = t & 31;
    const int lq = lane >> 2, lr = lane & 3;
    const int cw = (w & 3) * 32, nw = (w >> 2) * 64;

    for (int i = t; i < 16384; i += 256) {
        int c = i >> 7, d = i & 127;
        os_[CO_AS + c * 132 + d] = f32_tf32(g_e[((b * C + c) << 7) + d]);
    }
    for (int i = t; i < 16384; i += 256) {
        int d = i >> 7, n = i & 127;
        os_[CO_FS + d * 136 + n] = f32_tf32(g_y[((b * C + d) << 12) + nb + n]);
    }
    __syncthreads();

    float acc[2][8][4];
#pragma unroll
    for (int ct = 0; ct < 2; ct++)
#pragma unroll
        for (int nt = 0; nt < 8; nt++)
#pragma unroll
            for (int i = 0; i < 4; i++) acc[ct][nt][i] = 0.f;

#pragma unroll
    for (int ks = 0; ks < 16; ks++) {
        const int k = ks * 8;
        uint32_t a[2][4];
#pragma unroll
        for (int ct = 0; ct < 2; ct++) {
            int r = (cw + ct * 16 + lq) * 132 + k + lr;
            a[ct][0] = os_[CO_AS + r];
            a[ct][1] = os_[CO_AS + r + 8 * 132];
            a[ct][2] = os_[CO_AS + r + 4];
            a[ct][3] = os_[CO_AS + r + 8 * 132 + 4];
        }
#pragma unroll
        for (int nt = 0; nt < 8; nt++) {
            uint32_t b0 = os_[CO_FS + (k + lr) * 136 + nw + nt * 8 + lq];
            uint32_t b1 = os_[CO_FS + (k + lr + 4) * 136 + nw + nt * 8 + lq];
#pragma unroll
            for (int ct = 0; ct < 2; ct++)
                mma_tf32(acc[ct][nt], a[ct], b0, b1);
        }
    }

    const float g = gca[0];
#pragma unroll
    for (int ct = 0; ct < 2; ct++) {
#pragma unroll
        for (int rr = 0; rr < 2; rr++) {
            int c = cw + ct * 16 + lq + rr * 8;
            float* row = &out[((b * C + c) << 12) + nb + nw];
#pragma unroll
            for (int nt = 0; nt < 8; nt++) {
                int n = nt * 8 + lr * 2;
                red_add(&row[n],     g * acc[ct][nt][rr * 2]);
                red_add(&row[n + 1], g * acc[ct][nt][rr * 2 + 1]);
            }
        }
    }
}

// ---------------- K8: PAM: m-tile 128, n-chunk 64, 3-stage cp.async ----------
#define P_QS 0
#define P_KS 2560
#define P_VS 5824
#define P_SN 31936
#define P_WORDS 40640

__global__ __launch_bounds__(256, 1)
void pam_mma_kernel(const float* __restrict__ gpa, float* __restrict__ out) {
    extern __shared__ uint32_t ps[];
    const int b = blockIdx.y, m0 = blockIdx.x * 128;
    const int t = threadIdx.x;
    const int w = t >> 5, lane = t & 31;
    const int lq = lane >> 2, lr = lane & 3;
    const uint32_t sbase = (uint32_t)__cvta_generic_to_shared(ps);

    for (int i = t; i < 2048; i += 256) {
        int qc = i >> 7, m = i & 127;
        ps[P_QS + m * 20 + qc] = g_q[((b * CQK + qc) << 12) + m0 + m];
    }

    const int krow = t >> 4, kc4 = (t & 15) * 4;
    const uint32_t kdst = sbase + (P_KS + krow * 68 + kc4) * 4;
    const uint32_t* kgsrc = &g_k[((b * CQK + krow) << 12) + kc4];
    const uint32_t vdst = sbase + (P_VS + krow * 68 + kc4) * 4;
    const uint32_t* vgsrc = &g_v[((b * C + krow) << 12) + kc4];

    cp16(kdst, kgsrc);
#pragma unroll
    for (int p = 0; p < 8; p++)
        cp16(vdst + p * 16 * 68 * 4, vgsrc + (p << 16));
    cp_commit();
    cp16(kdst + 1088 * 4, kgsrc + 64);
#pragma unroll
    for (int p = 0; p < 8; p++)
        cp16(vdst + (8704 + p * 16 * 68) * 4, vgsrc + (p << 16) + 64);
    cp_commit();

    __syncthreads();

    uint32_t aq[2][4];
#pragma unroll
    for (int ks = 0; ks < 2; ks++) {
        int r = w * 16 + lq, c = ks * 8 + lr;
        aq[ks][0] = ps[P_QS + r * 20 + c];
        aq[ks][1] = ps[P_QS + (r + 8) * 20 + c];
        aq[ks][2] = ps[P_QS + r * 20 + c + 4];
        aq[ks][3] = ps[P_QS + (r + 8) * 20 + c + 4];
    }

    const int cw = (w & 3) * 32, mw = (w >> 2) * 64;

    const int aRow = lane & 15;
    const int aCol = (lane >> 4) << 2;
    const int bRow = ((lane >> 4) << 3) + (lane & 7);
    const int bCol = ((lane >> 3) & 1) << 2;
    uint32_t aOff[2], bOff[4];
#pragma unroll
    for (int ct = 0; ct < 2; ct++)
        aOff[ct] = (uint32_t)((cw + ct * 16 + aRow) * 68 + aCol);
#pragma unroll
    for (int p = 0; p < 4; p++)
        bOff[p] = (uint32_t)(P_SN + (mw + 16 * p + bRow) * 68 + bCol);

    float acc[2][8][4];
#pragma unroll
    for (int ct = 0; ct < 2; ct++)
#pragma unroll
        for (int mt = 0; mt < 8; mt++)
#pragma unroll
            for (int i = 0; i < 4; i++) acc[ct][mt][i] = 0.f;

    int sc = 0, sp = 2;
#pragma unroll 1
    for (int ch = 0; ch < 64; ch++) {
        cp_wait<1>();
        __syncthreads();

        if (ch + 2 < 64) {
            const int n2 = (ch + 2) * 64;
            cp16(kdst + sp * 1088 * 4, kgsrc + n2);
#pragma unroll
            for (int p = 0; p < 8; p++)
                cp16(vdst + (sp * 8704 + p * 16 * 68) * 4, vgsrc + (p << 16) + n2);
        }
        cp_commit();

        const uint32_t* ksb = ps + P_KS + sc * 1088;
        const uint32_t vWordBase = (uint32_t)(P_VS + sc * 8704);

        float e[8][4];
#pragma unroll
        for (int ni = 0; ni < 8; ni++) {
#pragma unroll
            for (int i = 0; i < 4; i++) e[ni][i] = 0.f;
#pragma unroll
            for (int ks = 0; ks < 2; ks++) {
                uint32_t b0 = ksb[(ks * 8 + lr) * 68 + ni * 8 + lq];
                uint32_t b1 = ksb[(ks * 8 + lr + 4) * 68 + ni * 8 + lq];
                mma_tf32(e[ni], aq[ks], b0, b1);
            }
        }
        {
            int m = w * 16 + lq;
#pragma unroll
            for (int ni = 0; ni < 8; ni++) {
                int n = ni * 8 + lr * 2;
                uint2 u0, u1;
                u0.x = f32_tf32(tanh_ap(e[ni][0]));
                u0.y = f32_tf32(tanh_ap(e[ni][1]));
                u1.x = f32_tf32(tanh_ap(e[ni][2]));
                u1.y = f32_tf32(tanh_ap(e[ni][3]));
                *(uint2*)&ps[P_SN + m * 68 + n]       = u0;
                *(uint2*)&ps[P_SN + (m + 8) * 68 + n] = u1;
            }
        }
        __syncthreads();

#pragma unroll
        for (int ks = 0; ks < 8; ks++) {
            const int k = ks * 8;
            uint32_t a[2][4], bb8[4][4];
#pragma unroll
            for (int ct = 0; ct < 2; ct++)
                ldsm4(a[ct], sbase + (vWordBase + aOff[ct] + k) * 4);
#pragma unroll
            for (int p = 0; p < 4; p++)
                ldsm4(bb8[p], sbase + (bOff[p] + k) * 4);
#pragma unroll
            for (int ct = 0; ct < 2; ct++)
#pragma unroll
                for (int mt = 0; mt < 8; mt++)
                    mma_tf32(acc[ct][mt], a[ct], bb8[mt >> 1][(mt & 1) * 2],
                             bb8[mt >> 1][(mt & 1) * 2 + 1]);
        }

        sc = (sc == 2) ? 0 : sc + 1;
        sp = (sp == 2) ? 0 : sp + 1;
    }

    const float g = gpa[0];
#pragma unroll
    for (int ct = 0; ct < 2; ct++) {
#pragma unroll
        for (int rr = 0; rr < 2; rr++) {
            int c = cw + ct * 16 + lq + rr * 8;
            float* row = &out[((b * C + c) << 12) + m0 + mw];
#pragma unroll
            for (int mt = 0; mt < 8; mt++) {
                int m = mt * 8 + lr * 2;
                red_add(&row[m],     g * acc[ct][mt][rr * 2]);
                red_add(&row[m + 1], g * acc[ct][mt][rr * 2 + 1]);
            }
        }
    }
}

// ---------------- launch (forked streams: CAM chain || qkv+PAM) --------------
extern "C" void kernel_launch(void* const* d_in, const int* in_sizes, int n_in,
                              void* d_out, int out_size) {
    const float* x       = (const float*)d_in[0];
    const float* conv_w  = (const float*)d_in[1];
    const float* bn_g    = (const float*)d_in[2];
    const float* bn_b    = (const float*)d_in[3];
    const float* q_w     = (const float*)d_in[4];
    const float* q_b     = (const float*)d_in[5];
    const float* k_w     = (const float*)d_in[6];
    const float* k_b     = (const float*)d_in[7];
    const float* v_w     = (const float*)d_in[8];
    const float* v_b     = (const float*)d_in[9];
    const float* gca     = (const float*)d_in[10];
    const float* gpa     = (const float*)d_in[11];
    float* out = (float*)d_out;

    static cudaStream_t sA = nullptr, sB = nullptr;
    static cudaEvent_t ev0 = nullptr, evA = nullptr, evB = nullptr;
    if (!sA) {
        cudaStreamCreateWithFlags(&sA, cudaStreamNonBlocking);
        cudaStreamCreateWithFlags(&sB, cudaStreamNonBlocking);
        cudaEventCreateWithFlags(&ev0, cudaEventDisableTiming);
        cudaEventCreateWithFlags(&evA, cudaEventDisableTiming);
        cudaEventCreateWithFlags(&evB, cudaEventDisableTiming);

        cudaFuncSetAttribute(conv_tc_kernel, cudaFuncAttributeMaxDynamicSharedMemorySize,
                             CONV_SMEM_WORDS * 4);
        cudaFuncSetAttribute(pam_mma_kernel, cudaFuncAttributeMaxDynamicSharedMemorySize,
                             P_WORDS * 4);
        cudaFuncSetAttribute(qkv_mma_kernel, cudaFuncAttributeMaxDynamicSharedMemorySize,
                             QK_WORDS * 4);
        cudaFuncSetAttribute(cam_energy_mma_kernel, cudaFuncAttributeMaxDynamicSharedMemorySize,
                             CE_WORDS * 4);
        cudaFuncSetAttribute(cam_out_mma_kernel, cudaFuncAttributeMaxDynamicSharedMemorySize,
                             CO_WORDS * 4);
    }

    // serial prologue on the launch stream
    wprep_kernel<<<576, 256>>>(conv_w);
    conv_tc_kernel<<<dim3(64, B), 256, CONV_SMEM_WORDS * 4>>>(x);
    bnstats1_kernel<<<512, 256>>>();
    bnrelu_kernel<<<2048, 256>>>(bn_g, bn_b, out);

    // fork
    cudaEventRecord(ev0, 0);
    cudaStreamWaitEvent(sA, ev0, 0);
    cudaStreamWaitEvent(sB, ev0, 0);

    // stream A: CAM chain (atomic adds into out)
    cam_energy_mma_kernel<<<dim3(ESPLIT, B), 256, CE_WORDS * 4, sA>>>();
    cam_reduce_kernel<<<dim3(C, B), 128, 0, sA>>>();
    cam_out_mma_kernel<<<dim3(32, B), 256, CO_WORDS * 4, sA>>>(gca, out);

    // stream B: qkv -> PAM (atomic adds into out)
    qkv_mma_kernel<<<dim3(64, B), 320, QK_WORDS * 4, sB>>>(q_w, q_b, k_w, k_b, v_w, v_b);
    pam_mma_kernel<<<dim3(32, B), 256, P_WORDS * 4, sB>>>(gpa, out);

    // join
    cudaEventRecord(evA, sA);
    cudaEventRecord(evB, sB);
    cudaStreamWaitEvent(0, evA, 0);
    cudaStreamWaitEvent(0, evB, 0);
}